// round 7
// baseline (speedup 1.0000x reference)
#include <cuda_runtime.h>
#include <cuda_bf16.h>
#include <math.h>
#include <stdint.h>

// ---------------- problem constants ----------------
#define TPLEN 600
#define TQLEN 60
#define BATCH 64
// H=256, H2=128, EMB=344

// ---------------- scratch ----------------
#define N_XP   (600LL*64*384)
#define N_XQ   (60LL*64*384)
#define N_HP   (600LL*64*256)
#define N_HQ   (60LL*64*256)
#define N_XPM  (600LL*64*512)
#define N_YQ   (60LL*64*512)
#define N_WCATB (128LL*384)          // u32 elements (bf16 pairs)

#define O_X0p  0LL
#define O_X0q  (O_X0p + N_XP)
#define O_Hp0  (O_X0q + N_XQ)
#define O_Hq0  (O_Hp0 + N_HP)
#define O_Hp1  (O_Hq0 + N_HQ)
#define O_Hq1  (O_Hp1 + N_HP)
#define O_aq   (O_Hq1 + N_HQ)
#define O_ap   (O_aq  + N_HQ)
#define O_xp   (O_ap  + N_HP)
#define O_Yq   (O_xp  + N_XPM)
#define O_WCB  (O_Yq  + N_YQ)
#define SCRATCH_TOTAL (O_WCB + N_WCATB)

__device__ __align__(16) float g_scratch[SCRATCH_TOTAL];

// ---------------- helpers ----------------
__device__ __forceinline__ float sigf(float x) { return 1.0f / (1.0f + __expf(-x)); }
__device__ __forceinline__ float tanh_ap(float x) {
    float y;
    asm("tanh.approx.f32 %0, %1;" : "=f"(y) : "f"(x));
    return y;
}
typedef unsigned long long ull;
__device__ __forceinline__ ull pack2(float x, float y) {
    ull r; asm("mov.b64 %0, {%1, %2};" : "=l"(r) : "f"(x), "f"(y)); return r;
}
__device__ __forceinline__ float2 unpack2(ull v) {
    float2 f; asm("mov.b64 {%0, %1}, %2;" : "=f"(f.x), "=f"(f.y) : "l"(v)); return f;
}
__device__ __forceinline__ ull fma2(ull a, ull b, ull c) {
    ull d; asm("fma.rn.f32x2 %0, %1, %2, %3;" : "=l"(d) : "l"(a), "l"(b), "l"(c)); return d;
}

// ---------------- GEMM: C[M,N] = A[M,K] @ W[N, wcol0:wcol0+K]^T (+ bias) ----------------
__global__ __launch_bounds__(256, 2) void gemm_bias(
    const float* __restrict__ A, const float* __restrict__ W,
    const float* __restrict__ bias, float* __restrict__ C,
    int M, int N, int K, int ldw, int wcol0, int hasBias)
{
    __shared__ float As[8][132];
    __shared__ float Ws[8][132];
    int bm = blockIdx.y, bn = blockIdx.x;
    int tid = threadIdx.x;
    int tm = tid >> 4, tn = tid & 15;

    int lrow = tid >> 1;
    int kq   = (tid & 1) * 4;

    const float* Ag = A + (long long)(bm * 128 + lrow) * K + kq;
    const float* Wg = W + (long long)(bn * 128 + lrow) * ldw + wcol0 + kq;

    float acc[8][8];
#pragma unroll
    for (int i = 0; i < 8; i++)
#pragma unroll
        for (int j = 0; j < 8; j++) acc[i][j] = 0.0f;

    for (int k0 = 0; k0 < K; k0 += 8) {
        float4 av = *(const float4*)(Ag + k0);
        float4 wv = *(const float4*)(Wg + k0);
        __syncthreads();
        As[kq + 0][lrow] = av.x; As[kq + 1][lrow] = av.y;
        As[kq + 2][lrow] = av.z; As[kq + 3][lrow] = av.w;
        Ws[kq + 0][lrow] = wv.x; Ws[kq + 1][lrow] = wv.y;
        Ws[kq + 2][lrow] = wv.z; Ws[kq + 3][lrow] = wv.w;
        __syncthreads();
#pragma unroll
        for (int kk = 0; kk < 8; kk++) {
            float4 a0 = *(const float4*)&As[kk][tm * 8];
            float4 a1 = *(const float4*)&As[kk][tm * 8 + 4];
            float4 b0 = *(const float4*)&Ws[kk][tn * 8];
            float4 b1 = *(const float4*)&Ws[kk][tn * 8 + 4];
            float ar[8] = {a0.x, a0.y, a0.z, a0.w, a1.x, a1.y, a1.z, a1.w};
            float br[8] = {b0.x, b0.y, b0.z, b0.w, b1.x, b1.y, b1.z, b1.w};
#pragma unroll
            for (int i = 0; i < 8; i++)
#pragma unroll
                for (int j = 0; j < 8; j++) acc[i][j] += ar[i] * br[j];
        }
    }

    float bv[8];
#pragma unroll
    for (int j = 0; j < 8; j++)
        bv[j] = hasBias ? bias[bn * 128 + tn * 8 + j] : 0.0f;

#pragma unroll
    for (int i = 0; i < 8; i++) {
        long long crow = (long long)(bm * 128 + tm * 8 + i) * N + bn * 128 + tn * 8;
        float4 s0 = make_float4(acc[i][0] + bv[0], acc[i][1] + bv[1], acc[i][2] + bv[2], acc[i][3] + bv[3]);
        float4 s1 = make_float4(acc[i][4] + bv[4], acc[i][5] + bv[5], acc[i][6] + bv[6], acc[i][7] + bv[7]);
        *(float4*)(C + crow) = s0;
        *(float4*)(C + crow + 4) = s1;
    }
}

// ---------------- weight pack for match scan ----------------
// WcatB[k][384] u32; bits[15:0]=bf16 of W(2c,k), bits[31:16]=bf16 of W(2c+1,k).
__global__ void make_wcatb(const float* __restrict__ Wh,
                           const float* __restrict__ Whh,
                           unsigned* __restrict__ out)
{
    int i = blockIdx.x * 256 + threadIdx.x;
    if (i >= 128 * 384) return;
    int k = i / 384, c = i % 384;
    int c0 = 2 * c, c1 = 2 * c + 1;
    float w0 = (c0 < 256) ? Wh[c0 * 128 + k] : Whh[(c0 - 256) * 128 + k];
    float w1 = (c1 < 256) ? Wh[c1 * 128 + k] : Whh[(c1 - 256) * 128 + k];
    unsigned lo = (unsigned)__bfloat16_as_ushort(__float2bfloat16(w0));
    unsigned hi = (unsigned)__bfloat16_as_ushort(__float2bfloat16(w1));
    out[i] = lo | (hi << 16);
}

// ---------------- pre-BiLSTM scan (one direction per CTA) ----------------
__global__ __launch_bounds__(384, 1) void pre_scan(
    const float* __restrict__ X, const float* __restrict__ mask,
    const float* __restrict__ Whh, float* __restrict__ Hout, int T)
{
    __shared__ __align__(16) float h_s[128];
    __shared__ __align__(16) float c_s[128];
    __shared__ float gates[384];
    int b = blockIdx.x & 63;
    int d = blockIdx.x >> 6;
    int j = threadIdx.x;

    float4 w[32];
    const float4* wrow = (const float4*)(Whh + j * 128);
#pragma unroll
    for (int i = 0; i < 32; i++) w[i] = wrow[i];

    if (j < 128) { h_s[j] = 0.f; c_s[j] = 0.f; }
    __syncthreads();

    for (int t = 0; t < T; t++) {
        int td = d ? (T - 1 - t) : t;
        float acc = X[((long long)td * BATCH + b) * 384 + j];
        const float4* h0 = (const float4*)h_s;
#pragma unroll 8
        for (int i = 0; i < 32; i++) {
            float4 x0 = h0[i];
            acc += w[i].x * x0.x + w[i].y * x0.y + w[i].z * x0.z + w[i].w * x0.w;
        }
        gates[j] = acc;
        __syncthreads();
        if (j < 128) {
            float ig = gates[j], fg = gates[128 + j], gg = gates[256 + j];
            float m = mask[td * BATCH + b];
            float c2 = (sigf(fg) * c_s[j] + sigf(ig) * tanhf(gg)) * m;
            float h2 = tanhf(c2);
            c_s[j] = c2;
            h_s[j] = h2;
            Hout[((long long)td * BATCH + b) * 256 + d * 128 + j] = h2;
        }
        __syncthreads();
    }
}

// ---------------- Match-LSTM scan (v4: register-resident weights) ----------------
// grid = 128 (b = bx&63, d = bx>>6), block = 768.
// thread = (cp = tid%384, kh = tid/384); weights preloaded to 64 u32 regs each.
#define MS_YQ    0                       // 60*512
#define MS_AQ    (MS_YQ + 60 * 512)      // 60*256
#define MS_WA    (MS_AQ + 60 * 256)      // 256
#define MS_U     (MS_WA + 256)           // 256
#define MS_G     (MS_U + 256)            // 512
#define MS_HS    (MS_G + 512)            // 256  (128 ull h-splats)
#define MS_AL    (MS_HS + 256)           // 64   (scalar logits)
#define MS_AL2   (MS_AL + 64)            // 128  (64 ull splatted alphas)
#define MS_PART  (MS_AL2 + 128)          // 768  (384 ull partials)
#define MS_TOTAL (MS_PART + 768)
#define MATCH_SMEM_BYTES (MS_TOTAL * 4)

__global__ __launch_bounds__(768, 1) void match_scan(
    const float* __restrict__ ap,       // [600,64,256]
    const float* __restrict__ xp,       // [600,64,512]
    const float* __restrict__ aq,       // [60,64,256]
    const float* __restrict__ Yq,       // [60,64,512]
    const unsigned* __restrict__ WcatB, // [128,384] packed bf16 col-pairs
    const float* __restrict__ Wa,       // [256]
    const float* __restrict__ ba,       // [1]
    const float* __restrict__ mask,     // [600,64]
    float* __restrict__ out)            // [600,64,256]
{
    extern __shared__ __align__(16) float sm[];
    float* Yq_s = sm + MS_YQ;
    float* aq_s = sm + MS_AQ;
    float* Wa_s = sm + MS_WA;
    float* u_s  = sm + MS_U;
    float* g_s  = sm + MS_G;
    ull*   hsp  = (ull*)(sm + MS_HS);
    float* al_s = sm + MS_AL;
    ull*   al2  = (ull*)(sm + MS_AL2);
    ull*   part = (ull*)(sm + MS_PART);

    int b = blockIdx.x & 63;
    int d = blockIdx.x >> 6;
    int tid = threadIdx.x;
    int lane = tid & 31;
    int cp = (tid < 384) ? tid : (tid - 384);
    int kh = (tid < 384) ? 0 : 1;

    // ---- preload weights into registers: w[j] = WcatB[(kh*64+j)*384 + cp]
    unsigned w[64];
    {
        const unsigned* wp = WcatB + (kh * 64) * 384 + cp;
#pragma unroll
        for (int j = 0; j < 64; j++) w[j] = wp[j * 384];
    }

    // ---- stage per-batch tensors to smem
    for (int idx = tid; idx < 60 * 128; idx += 768) {
        int tq = idx >> 7, jj = idx & 127;
        ((float4*)Yq_s)[idx] = *(const float4*)(Yq + ((long long)tq * BATCH + b) * 512 + jj * 4);
    }
    for (int idx = tid; idx < 60 * 64; idx += 768) {
        int tq = idx >> 6, jj = idx & 63;
        ((float4*)aq_s)[idx] = *(const float4*)(aq + ((long long)tq * BATCH + b) * 256 + jj * 4);
    }
    if (tid < 256) Wa_s[tid] = Wa[tid];
    if (tid < 128) hsp[tid] = 0ull;
    float bav = ba[0];
    float c_reg = 0.f;   // cell state for tid<128 (unit k = tid)
    __syncthreads();

    const ull* hk = hsp + kh * 64;

    for (int t = 0; t < TPLEN; t++) {
        int td = d ? (TPLEN - 1 - t) : t;

        // ---- Phase A: partial matvec, weights from registers, h from smem
        ull acc;
        {
            if (kh == 0) {
                float2 init;
                if (cp < 128)
                    init = *(const float2*)(ap + ((long long)td * BATCH + b) * 256 + 2 * cp);
                else
                    init = *(const float2*)(xp + ((long long)td * BATCH + b) * 512 + 2 * (cp - 128));
                acc = pack2(init.x, init.y);
            } else {
                acc = pack2(0.f, 0.f);
            }
#pragma unroll
            for (int j = 0; j < 64; j++) {
                unsigned v = w[j];
                ull w2 = pack2(__uint_as_float(v << 16),
                               __uint_as_float(v & 0xFFFF0000u));
                acc = fma2(w2, hk[j], acc);
            }
            if (kh) part[cp] = acc;
        }
        __syncthreads();

        // ---- combine k-halves (threads 0..383); u cols to smem
        if (tid < 384) {
            float2 a = unpack2(acc), p = unpack2(part[tid]);
            a.x += p.x; a.y += p.y;
            acc = pack2(a.x, a.y);
            if (tid < 128) *(float2*)&u_s[2 * tid] = a;
        }
        __syncthreads();

        // ---- Phase 2: logits e[tq] = ba + sum_i Wa[i]*tanh(aq[tq,i] + u[i])
        {
            int tq = tid >> 3, l8 = tid & 7;
            if (tq < TQLEN) {
                const float* aqr = aq_s + tq * 256;
                float a0 = 0.f;
#pragma unroll
                for (int ii = 0; ii < 32; ii++) {
                    int i = l8 * 32 + ((ii + lane) & 31);  // bank-stagger
                    a0 += Wa_s[i] * tanh_ap(aqr[i] + u_s[i]);
                }
                a0 += __shfl_xor_sync(0xffffffffu, a0, 1);
                a0 += __shfl_xor_sync(0xffffffffu, a0, 2);
                a0 += __shfl_xor_sync(0xffffffffu, a0, 4);
                if (l8 == 0) al_s[tq] = a0 + bav;
            }
        }
        __syncthreads();

        // ---- Phase 3: softmax over TQ (warp 0), write splatted alphas
        if (tid < 32) {
            float e0 = (lane < TQLEN) ? al_s[lane] : -1e30f;
            float e1 = (lane + 32 < TQLEN) ? al_s[lane + 32] : -1e30f;
            float mx = fmaxf(e0, e1);
#pragma unroll
            for (int o = 16; o; o >>= 1) mx = fmaxf(mx, __shfl_xor_sync(0xffffffffu, mx, o));
            float s0 = (lane < TQLEN) ? __expf(e0 - mx) : 0.f;
            float s1 = (lane + 32 < TQLEN) ? __expf(e1 - mx) : 0.f;
            float s = s0 + s1;
#pragma unroll
            for (int o = 16; o; o >>= 1) s += __shfl_xor_sync(0xffffffffu, s, o);
            float inv = 1.0f / s;
            if (lane < TQLEN) { float v = s0 * inv; al2[lane] = pack2(v, v); }
            if (lane + 32 < TQLEN) { float v = s1 * inv; al2[lane + 32] = pack2(v, v); }
        }
        __syncthreads();

        // ---- Phase 4: gates += sum_tq alpha[tq] * Yq[tq]; store to g_s
        if (tid >= 128 && tid < 384) {
            int gp = tid - 128;  // gate col pair (2gp, 2gp+1)
            const ull* yq2 = (const ull*)Yq_s + gp;
#pragma unroll 4
            for (int tq = 0; tq < TQLEN; tq++) {
                acc = fma2(al2[tq], yq2[tq * 256], acc);
            }
            float2 f = unpack2(acc);
            *(float2*)&g_s[2 * gp] = f;
        }
        __syncthreads();

        // ---- Phase 5: LSTM cell (c in registers), write h splats + output
        if (tid < 128) {
            int k = tid;
            float ig = g_s[k], fg = g_s[128 + k], gg = g_s[256 + k], og = g_s[384 + k];
            float m = mask[td * BATCH + b];
            float c2 = sigf(fg) * c_reg + sigf(ig) * tanhf(gg);
            float h2 = sigf(og) * tanhf(c2);
            c2 *= m; h2 *= m;
            c_reg = c2;
            hsp[k] = pack2(h2, h2);
            out[((long long)td * BATCH + b) * 256 + d * 128 + k] = h2;
        }
        __syncthreads();
    }
}

// ---------------- host ----------------
static void launch_gemm(const float* A, const float* W, const float* bias, float* C,
                        int M, int N, int K, int ldw, int wcol0)
{
    dim3 g(N / 128, M / 128);
    gemm_bias<<<g, 256>>>(A, W, bias, C, M, N, K, ldw, wcol0, bias != nullptr ? 1 : 0);
}

extern "C" void kernel_launch(void* const* d_in, const int* in_sizes, int n_in,
                              void* d_out, int out_size)
{
    const float* passage  = (const float*)d_in[0];
    const float* question = (const float*)d_in[1];
    const float* mask_p   = (const float*)d_in[2];
    const float* mask_q   = (const float*)d_in[3];
    const float* pre0_Wih = (const float*)d_in[4];
    const float* pre0_Whh = (const float*)d_in[5];
    const float* pre0_b   = (const float*)d_in[6];
    const float* pre1_Wih = (const float*)d_in[7];
    const float* pre1_Whh = (const float*)d_in[8];
    const float* pre1_b   = (const float*)d_in[9];
    const float* mq_Wq    = (const float*)d_in[10];
    const float* mq_Wp    = (const float*)d_in[11];
    const float* mq_bp    = (const float*)d_in[12];
    const float* mq_Wh    = (const float*)d_in[13];
    const float* mq_Wa    = (const float*)d_in[14];
    const float* mq_ba    = (const float*)d_in[15];
    const float* mq_Wih   = (const float*)d_in[16];
    const float* mq_Whh   = (const float*)d_in[17];
    const float* mq_b     = (const float*)d_in[18];
    float* out = (float*)d_out;

    float* s = nullptr;
    cudaGetSymbolAddress((void**)&s, g_scratch);

    float* X0p = s + O_X0p;
    float* X0q = s + O_X0q;
    float* Hp0 = s + O_Hp0;
    float* Hq0 = s + O_Hq0;
    float* Hp1 = s + O_Hp1;
    float* Hq1 = s + O_Hq1;
    float* aqb = s + O_aq;
    float* apb = s + O_ap;
    float* xpb = s + O_xp;
    float* Yqb = s + O_Yq;
    unsigned* WcatB = (unsigned*)(s + O_WCB);

    cudaFuncSetAttribute(match_scan, cudaFuncAttributeMaxDynamicSharedMemorySize,
                         MATCH_SMEM_BYTES);

    // bf16 weight pack for the match scan (independent of data path)
    make_wcatb<<<(128 * 384 + 255) / 256, 256>>>(mq_Wh, mq_Whh, WcatB);

    // ---- pre layer 0 (i,f,g gates only: 384 rows) ----
    launch_gemm(passage,  pre0_Wih, pre0_b, X0p, TPLEN * BATCH, 384, 344, 344, 0);
    launch_gemm(question, pre0_Wih, pre0_b, X0q, TQLEN * BATCH, 384, 344, 344, 0);
    pre_scan<<<2 * BATCH, 384>>>(X0p, mask_p, pre0_Whh, Hp0, TPLEN);
    pre_scan<<<2 * BATCH, 384>>>(X0q, mask_q, pre0_Whh, Hq0, TQLEN);

    // ---- pre layer 1 ----
    launch_gemm(Hp0, pre1_Wih, pre1_b, X0p, TPLEN * BATCH, 384, 256, 256, 0);
    launch_gemm(Hq0, pre1_Wih, pre1_b, X0q, TQLEN * BATCH, 384, 256, 256, 0);
    pre_scan<<<2 * BATCH, 384>>>(X0p, mask_p, pre1_Whh, Hp1, TPLEN);
    pre_scan<<<2 * BATCH, 384>>>(X0q, mask_q, pre1_Whh, Hq1, TQLEN);

    // ---- match precompute ----
    launch_gemm(Hq1, mq_Wq, nullptr, aqb, TQLEN * BATCH, 256, 256, 256, 0);
    launch_gemm(Hp1, mq_Wp, mq_bp,   apb, TPLEN * BATCH, 256, 256, 256, 0);
    launch_gemm(Hp1, mq_Wih, mq_b,   xpb, TPLEN * BATCH, 512, 256, 512, 0);
    launch_gemm(Hq1, mq_Wih, nullptr, Yqb, TQLEN * BATCH, 512, 256, 512, 256);

    // ---- match scan ----
    match_scan<<<2 * BATCH, 768, MATCH_SMEM_BYTES>>>(
        apb, xpb, aqb, Yqb, WcatB, mq_Wa, mq_ba, mask_p, out);

    (void)in_sizes; (void)n_in; (void)out_size;
}

// round 9
// speedup vs baseline: 1.1532x; 1.1532x over previous
#include <cuda_runtime.h>
#include <cuda_bf16.h>
#include <math.h>
#include <stdint.h>

// ---------------- problem constants ----------------
#define TPLEN 600
#define TQLEN 60
#define BATCH 64
// H=256, H2=128, EMB=344

// ---------------- scratch ----------------
#define N_XP   (600LL*64*384)
#define N_XQ   (60LL*64*384)
#define N_HP   (600LL*64*256)
#define N_HQ   (60LL*64*256)
#define N_XPM  (600LL*64*512)
#define N_YQ   (60LL*64*512)
#define N_WCATB (128LL*384)          // u32 elements (bf16 pairs)

#define O_X0p  0LL
#define O_X0q  (O_X0p + N_XP)
#define O_Hp0  (O_X0q + N_XQ)
#define O_Hq0  (O_Hp0 + N_HP)
#define O_Hp1  (O_Hq0 + N_HQ)
#define O_Hq1  (O_Hp1 + N_HP)
#define O_aq   (O_Hq1 + N_HQ)
#define O_ap   (O_aq  + N_HQ)
#define O_xp   (O_ap  + N_HP)
#define O_Yq   (O_xp  + N_XPM)
#define O_WCB  (O_Yq  + N_YQ)
#define SCRATCH_TOTAL (O_WCB + N_WCATB)

__device__ __align__(16) float g_scratch[SCRATCH_TOTAL];

// ---------------- helpers ----------------
__device__ __forceinline__ float sigf(float x) { return 1.0f / (1.0f + __expf(-x)); }
__device__ __forceinline__ float tanh_ap(float x) {
    float y;
    asm("tanh.approx.f32 %0, %1;" : "=f"(y) : "f"(x));
    return y;
}
typedef unsigned long long ull;
__device__ __forceinline__ ull pack2(float x, float y) {
    ull r; asm("mov.b64 %0, {%1, %2};" : "=l"(r) : "f"(x), "f"(y)); return r;
}
__device__ __forceinline__ float2 unpack2(ull v) {
    float2 f; asm("mov.b64 {%0, %1}, %2;" : "=f"(f.x), "=f"(f.y) : "l"(v)); return f;
}
__device__ __forceinline__ ull fma2(ull a, ull b, ull c) {
    ull d; asm("fma.rn.f32x2 %0, %1, %2, %3;" : "=l"(d) : "l"(a), "l"(b), "l"(c)); return d;
}
// expand packed bf16 pair (lo,hi halves of u32) to f32x2
__device__ __forceinline__ ull bf2(unsigned v) {
    return pack2(__uint_as_float(v << 16), __uint_as_float(v & 0xFFFF0000u));
}

// ---------------- GEMM: C[M,N] = A[M,K] @ W[N, wcol0:wcol0+K]^T (+ bias) ----------------
// Software-pipelined: next k-octet prefetched into registers during compute.
__global__ __launch_bounds__(256, 2) void gemm_bias(
    const float* __restrict__ A, const float* __restrict__ W,
    const float* __restrict__ bias, float* __restrict__ C,
    int M, int N, int K, int ldw, int wcol0, int hasBias)
{
    __shared__ float As[8][132];
    __shared__ float Ws[8][132];
    int bm = blockIdx.y, bn = blockIdx.x;
    int tid = threadIdx.x;
    int tm = tid >> 4, tn = tid & 15;

    int lrow = tid >> 1;
    int kq   = (tid & 1) * 4;

    const float* Ag = A + (long long)(bm * 128 + lrow) * K + kq;
    const float* Wg = W + (long long)(bn * 128 + lrow) * ldw + wcol0 + kq;

    float acc[8][8];
#pragma unroll
    for (int i = 0; i < 8; i++)
#pragma unroll
        for (int j = 0; j < 8; j++) acc[i][j] = 0.0f;

    // pipeline: preload first octet
    float4 av = *(const float4*)Ag;
    float4 wv = *(const float4*)Wg;

    for (int k0 = 0; k0 < K; k0 += 8) {
        __syncthreads();
        As[kq + 0][lrow] = av.x; As[kq + 1][lrow] = av.y;
        As[kq + 2][lrow] = av.z; As[kq + 3][lrow] = av.w;
        Ws[kq + 0][lrow] = wv.x; Ws[kq + 1][lrow] = wv.y;
        Ws[kq + 2][lrow] = wv.z; Ws[kq + 3][lrow] = wv.w;
        __syncthreads();
        if (k0 + 8 < K) {
            av = *(const float4*)(Ag + k0 + 8);
            wv = *(const float4*)(Wg + k0 + 8);
        }
#pragma unroll
        for (int kk = 0; kk < 8; kk++) {
            float4 a0 = *(const float4*)&As[kk][tm * 8];
            float4 a1 = *(const float4*)&As[kk][tm * 8 + 4];
            float4 b0 = *(const float4*)&Ws[kk][tn * 8];
            float4 b1 = *(const float4*)&Ws[kk][tn * 8 + 4];
            float ar[8] = {a0.x, a0.y, a0.z, a0.w, a1.x, a1.y, a1.z, a1.w};
            float br[8] = {b0.x, b0.y, b0.z, b0.w, b1.x, b1.y, b1.z, b1.w};
#pragma unroll
            for (int i = 0; i < 8; i++)
#pragma unroll
                for (int j = 0; j < 8; j++) acc[i][j] += ar[i] * br[j];
        }
    }

    float bv[8];
#pragma unroll
    for (int j = 0; j < 8; j++)
        bv[j] = hasBias ? bias[bn * 128 + tn * 8 + j] : 0.0f;

#pragma unroll
    for (int i = 0; i < 8; i++) {
        long long crow = (long long)(bm * 128 + tm * 8 + i) * N + bn * 128 + tn * 8;
        float4 s0 = make_float4(acc[i][0] + bv[0], acc[i][1] + bv[1], acc[i][2] + bv[2], acc[i][3] + bv[3]);
        float4 s1 = make_float4(acc[i][4] + bv[4], acc[i][5] + bv[5], acc[i][6] + bv[6], acc[i][7] + bv[7]);
        *(float4*)(C + crow) = s0;
        *(float4*)(C + crow + 4) = s1;
    }
}

// ---------------- weight pack for match scan ----------------
// WcatB[k][384] u32; bits[15:0]=bf16 of W(2c,k), bits[31:16]=bf16 of W(2c+1,k).
__global__ void make_wcatb(const float* __restrict__ Wh,
                           const float* __restrict__ Whh,
                           unsigned* __restrict__ out)
{
    int i = blockIdx.x * 256 + threadIdx.x;
    if (i >= 128 * 384) return;
    int k = i / 384, c = i % 384;
    int c0 = 2 * c, c1 = 2 * c + 1;
    float w0 = (c0 < 256) ? Wh[c0 * 128 + k] : Whh[(c0 - 256) * 128 + k];
    float w1 = (c1 < 256) ? Wh[c1 * 128 + k] : Whh[(c1 - 256) * 128 + k];
    unsigned lo = (unsigned)__bfloat16_as_ushort(__float2bfloat16(w0));
    unsigned hi = (unsigned)__bfloat16_as_ushort(__float2bfloat16(w1));
    out[i] = lo | (hi << 16);
}

// ---------------- pre-BiLSTM scan (one direction per CTA) ----------------
__global__ __launch_bounds__(384, 1) void pre_scan(
    const float* __restrict__ X, const float* __restrict__ mask,
    const float* __restrict__ Whh, float* __restrict__ Hout, int T)
{
    __shared__ __align__(16) float h_s[128];
    __shared__ __align__(16) float c_s[128];
    __shared__ float gates[384];
    int b = blockIdx.x & 63;
    int d = blockIdx.x >> 6;
    int j = threadIdx.x;

    float4 w[32];
    const float4* wrow = (const float4*)(Whh + j * 128);
#pragma unroll
    for (int i = 0; i < 32; i++) w[i] = wrow[i];

    if (j < 128) { h_s[j] = 0.f; c_s[j] = 0.f; }
    __syncthreads();

    for (int t = 0; t < T; t++) {
        int td = d ? (T - 1 - t) : t;
        float acc = X[((long long)td * BATCH + b) * 384 + j];
        const float4* h0 = (const float4*)h_s;
#pragma unroll 8
        for (int i = 0; i < 32; i++) {
            float4 x0 = h0[i];
            acc += w[i].x * x0.x + w[i].y * x0.y + w[i].z * x0.z + w[i].w * x0.w;
        }
        gates[j] = acc;
        __syncthreads();
        if (j < 128) {
            float ig = gates[j], fg = gates[128 + j], gg = gates[256 + j];
            float m = mask[td * BATCH + b];
            float c2 = (sigf(fg) * c_s[j] + sigf(ig) * tanhf(gg)) * m;
            float h2 = tanhf(c2);
            c_s[j] = c2;
            h_s[j] = h2;
            Hout[((long long)td * BATCH + b) * 256 + d * 128 + j] = h2;
        }
        __syncthreads();
    }
}

// ---------------- Match-LSTM scan (v5: 512 thr, bf16 global weights, dual accumulators) ----------------
// grid = 128 (b = bx&63, d = bx>>6), block = 512.
#define MS_YQ    0                       // 60*512
#define MS_AQ    (MS_YQ + 60 * 512)      // 60*256
#define MS_WA    (MS_AQ + 60 * 256)      // 256
#define MS_U     (MS_WA + 256)           // 256
#define MS_G     (MS_U + 256)            // 512
#define MS_HS    (MS_G + 512)            // 256  (128 ull h-splats)
#define MS_AL    (MS_HS + 256)           // 64   (scalar logits)
#define MS_AL2   (MS_AL + 64)            // 128  (64 ull splatted alphas)
#define MS_TOTAL (MS_AL2 + 128)
#define MATCH_SMEM_BYTES (MS_TOTAL * 4)

__global__ __launch_bounds__(512, 1) void match_scan(
    const float* __restrict__ ap,       // [600,64,256]
    const float* __restrict__ xp,       // [600,64,512]
    const float* __restrict__ aq,       // [60,64,256]
    const float* __restrict__ Yq,       // [60,64,512]
    const unsigned* __restrict__ WcatB, // [128,384] packed bf16 col-pairs
    const float* __restrict__ Wa,       // [256]
    const float* __restrict__ ba,       // [1]
    const float* __restrict__ mask,     // [600,64]
    float* __restrict__ out)            // [600,64,256]
{
    extern __shared__ __align__(16) float sm[];
    float* Yq_s = sm + MS_YQ;
    float* aq_s = sm + MS_AQ;
    float* Wa_s = sm + MS_WA;
    float* u_s  = sm + MS_U;
    float* g_s  = sm + MS_G;
    ull*   hsp  = (ull*)(sm + MS_HS);
    float* al_s = sm + MS_AL;
    ull*   al2  = (ull*)(sm + MS_AL2);

    int b = blockIdx.x & 63;
    int d = blockIdx.x >> 6;
    int tid = threadIdx.x;
    int lane = tid & 31;

    // stage per-batch tensors to smem
    for (int idx = tid; idx < 60 * 128; idx += 512) {
        int tq = idx >> 7, jj = idx & 127;
        ((float4*)Yq_s)[idx] = *(const float4*)(Yq + ((long long)tq * BATCH + b) * 512 + jj * 4);
    }
    for (int idx = tid; idx < 60 * 64; idx += 512) {
        int tq = idx >> 6, jj = idx & 63;
        ((float4*)aq_s)[idx] = *(const float4*)(aq + ((long long)tq * BATCH + b) * 256 + jj * 4);
    }
    if (tid < 256) Wa_s[tid] = Wa[tid];
    if (tid < 128) hsp[tid] = 0ull;
    float bav = ba[0];
    float c_reg = 0.f;   // cell state for tid<128 (unit k = tid)
    __syncthreads();

    for (int t = 0; t < TPLEN; t++) {
        int td = d ? (TPLEN - 1 - t) : t;

        // ---- Phase A: [u | gates](768 cols) = init + h @ Wcat; dual accumulators
        ull acc = 0;
        if (tid < 384) {
            int cp = tid;
            float2 init;
            if (cp < 128)
                init = *(const float2*)(ap + ((long long)td * BATCH + b) * 256 + 2 * cp);
            else
                init = *(const float2*)(xp + ((long long)td * BATCH + b) * 512 + 2 * (cp - 128));
            ull a0 = pack2(init.x, init.y);
            ull a1 = pack2(0.f, 0.f);
            const unsigned* wp = WcatB + cp;
#pragma unroll 8
            for (int j = 0; j < 64; j++) {
                unsigned v0 = wp[(2 * j) * 384];
                unsigned v1 = wp[(2 * j + 1) * 384];
                a0 = fma2(bf2(v0), hsp[2 * j], a0);
                a1 = fma2(bf2(v1), hsp[2 * j + 1], a1);
            }
            float2 f0 = unpack2(a0), f1 = unpack2(a1);
            f0.x += f1.x; f0.y += f1.y;
            acc = pack2(f0.x, f0.y);
            if (cp < 128) *(float2*)&u_s[2 * cp] = f0;
        }
        __syncthreads();

        // ---- Phase 2: logits e[tq] = ba + sum_i Wa[i]*tanh(aq[tq,i] + u[i])
        {
            int tq = tid >> 3, l8 = tid & 7;
            if (tq < TQLEN) {
                const float* aqr = aq_s + tq * 256;
                float a0 = 0.f;
#pragma unroll
                for (int ii = 0; ii < 32; ii++) {
                    int i = l8 * 32 + ((ii + lane) & 31);  // bank-stagger
                    a0 += Wa_s[i] * tanh_ap(aqr[i] + u_s[i]);
                }
                a0 += __shfl_xor_sync(0xffffffffu, a0, 1);
                a0 += __shfl_xor_sync(0xffffffffu, a0, 2);
                a0 += __shfl_xor_sync(0xffffffffu, a0, 4);
                if (l8 == 0) al_s[tq] = a0 + bav;
            }
        }
        __syncthreads();

        // ---- Phase 3: softmax over TQ (warp 0), write splatted alphas
        if (tid < 32) {
            float e0 = (lane < TQLEN) ? al_s[lane] : -1e30f;
            float e1 = (lane + 32 < TQLEN) ? al_s[lane + 32] : -1e30f;
            float mx = fmaxf(e0, e1);
#pragma unroll
            for (int o = 16; o; o >>= 1) mx = fmaxf(mx, __shfl_xor_sync(0xffffffffu, mx, o));
            float s0 = (lane < TQLEN) ? __expf(e0 - mx) : 0.f;
            float s1 = (lane + 32 < TQLEN) ? __expf(e1 - mx) : 0.f;
            float s = s0 + s1;
#pragma unroll
            for (int o = 16; o; o >>= 1) s += __shfl_xor_sync(0xffffffffu, s, o);
            float inv = 1.0f / s;
            if (lane < TQLEN) { float v = s0 * inv; al2[lane] = pack2(v, v); }
            if (lane + 32 < TQLEN) { float v = s1 * inv; al2[lane + 32] = pack2(v, v); }
        }
        __syncthreads();

        // ---- Phase 4: gates += sum_tq alpha[tq] * Yq[tq]; dual accumulators
        if (tid >= 128 && tid < 384) {
            int gp = tid - 128;  // gate col pair (2gp, 2gp+1)
            const ull* yq2 = (const ull*)Yq_s + gp;
            ull a0 = acc;
            ull a1 = pack2(0.f, 0.f);
#pragma unroll 4
            for (int tq = 0; tq < TQLEN; tq += 2) {
                a0 = fma2(al2[tq],     yq2[tq * 256],       a0);
                a1 = fma2(al2[tq + 1], yq2[(tq + 1) * 256], a1);
            }
            float2 f0 = unpack2(a0), f1 = unpack2(a1);
            f0.x += f1.x; f0.y += f1.y;
            *(float2*)&g_s[2 * gp] = f0;
        }
        __syncthreads();

        // ---- Phase 5: LSTM cell (c in registers), write h splats + output
        if (tid < 128) {
            int k = tid;
            float ig = g_s[k], fg = g_s[128 + k], gg = g_s[256 + k], og = g_s[384 + k];
            float m = mask[td * BATCH + b];
            float c2 = sigf(fg) * c_reg + sigf(ig) * tanhf(gg);
            float h2 = sigf(og) * tanhf(c2);
            c2 *= m; h2 *= m;
            c_reg = c2;
            hsp[k] = pack2(h2, h2);
            out[((long long)td * BATCH + b) * 256 + d * 128 + k] = h2;
        }
        __syncthreads();
    }
}

// ---------------- host ----------------
static void launch_gemm(const float* A, const float* W, const float* bias, float* C,
                        int M, int N, int K, int ldw, int wcol0)
{
    dim3 g(N / 128, M / 128);
    gemm_bias<<<g, 256>>>(A, W, bias, C, M, N, K, ldw, wcol0, bias != nullptr ? 1 : 0);
}

extern "C" void kernel_launch(void* const* d_in, const int* in_sizes, int n_in,
                              void* d_out, int out_size)
{
    const float* passage  = (const float*)d_in[0];
    const float* question = (const float*)d_in[1];
    const float* mask_p   = (const float*)d_in[2];
    const float* mask_q   = (const float*)d_in[3];
    const float* pre0_Wih = (const float*)d_in[4];
    const float* pre0_Whh = (const float*)d_in[5];
    const float* pre0_b   = (const float*)d_in[6];
    const float* pre1_Wih = (const float*)d_in[7];
    const float* pre1_Whh = (const float*)d_in[8];
    const float* pre1_b   = (const float*)d_in[9];
    const float* mq_Wq    = (const float*)d_in[10];
    const float* mq_Wp    = (const float*)d_in[11];
    const float* mq_bp    = (const float*)d_in[12];
    const float* mq_Wh    = (const float*)d_in[13];
    const float* mq_Wa    = (const float*)d_in[14];
    const float* mq_ba    = (const float*)d_in[15];
    const float* mq_Wih   = (const float*)d_in[16];
    const float* mq_Whh   = (const float*)d_in[17];
    const float* mq_b     = (const float*)d_in[18];
    float* out = (float*)d_out;

    float* s = nullptr;
    cudaGetSymbolAddress((void**)&s, g_scratch);

    float* X0p = s + O_X0p;
    float* X0q = s + O_X0q;
    float* Hp0 = s + O_Hp0;
    float* Hq0 = s + O_Hq0;
    float* Hp1 = s + O_Hp1;
    float* Hq1 = s + O_Hq1;
    float* aqb = s + O_aq;
    float* apb = s + O_ap;
    float* xpb = s + O_xp;
    float* Yqb = s + O_Yq;
    unsigned* WcatB = (unsigned*)(s + O_WCB);

    cudaFuncSetAttribute(match_scan, cudaFuncAttributeMaxDynamicSharedMemorySize,
                         MATCH_SMEM_BYTES);

    // bf16 weight pack for the match scan (independent of data path)
    make_wcatb<<<(128 * 384 + 255) / 256, 256>>>(mq_Wh, mq_Whh, WcatB);

    // ---- pre layer 0 (i,f,g gates only: 384 rows) ----
    launch_gemm(passage,  pre0_Wih, pre0_b, X0p, TPLEN * BATCH, 384, 344, 344, 0);
    launch_gemm(question, pre0_Wih, pre0_b, X0q, TQLEN * BATCH, 384, 344, 344, 0);
    pre_scan<<<2 * BATCH, 384>>>(X0p, mask_p, pre0_Whh, Hp0, TPLEN);
    pre_scan<<<2 * BATCH, 384>>>(X0q, mask_q, pre0_Whh, Hq0, TQLEN);

    // ---- pre layer 1 ----
    launch_gemm(Hp0, pre1_Wih, pre1_b, X0p, TPLEN * BATCH, 384, 256, 256, 0);
    launch_gemm(Hq0, pre1_Wih, pre1_b, X0q, TQLEN * BATCH, 384, 256, 256, 0);
    pre_scan<<<2 * BATCH, 384>>>(X0p, mask_p, pre1_Whh, Hp1, TPLEN);
    pre_scan<<<2 * BATCH, 384>>>(X0q, mask_q, pre1_Whh, Hq1, TQLEN);

    // ---- match precompute ----
    launch_gemm(Hq1, mq_Wq, nullptr, aqb, TQLEN * BATCH, 256, 256, 256, 0);
    launch_gemm(Hp1, mq_Wp, mq_bp,   apb, TPLEN * BATCH, 256, 256, 256, 0);
    launch_gemm(Hp1, mq_Wih, mq_b,   xpb, TPLEN * BATCH, 512, 256, 512, 0);
    launch_gemm(Hq1, mq_Wih, nullptr, Yqb, TQLEN * BATCH, 512, 256, 512, 256);

    // ---- match scan ----
    match_scan<<<2 * BATCH, 512, MATCH_SMEM_BYTES>>>(
        apb, xpb, aqb, Yqb, WcatB, mq_Wa, mq_ba, mask_p, out);

    (void)in_sizes; (void)n_in; (void)out_size;
}

// round 10
// speedup vs baseline: 1.2136x; 1.0524x over previous
#include <cuda_runtime.h>
#include <cuda_bf16.h>
#include <math.h>
#include <stdint.h>

// ---------------- problem constants ----------------
#define TPLEN 600
#define TQLEN 60
#define BATCH 64
// H=256, H2=128, EMB=344

// ---------------- scratch ----------------
#define N_XP   (600LL*64*384)
#define N_XQ   (60LL*64*384)
#define N_HP   (600LL*64*256)
#define N_HQ   (60LL*64*256)
#define N_XPM  (600LL*64*512)
#define N_YQ   (60LL*64*512)
#define N_WCATB (128LL*384)          // u32 elements (bf16 pairs), k-blocked layout

#define O_X0p  0LL
#define O_X0q  (O_X0p + N_XP)
#define O_Hp0  (O_X0q + N_XQ)
#define O_Hq0  (O_Hp0 + N_HP)
#define O_Hp1  (O_Hq0 + N_HQ)
#define O_Hq1  (O_Hp1 + N_HP)
#define O_aq   (O_Hq1 + N_HQ)
#define O_ap   (O_aq  + N_HQ)
#define O_xp   (O_ap  + N_HP)
#define O_Yq   (O_xp  + N_XPM)
#define O_WCB  (O_Yq  + N_YQ)
#define SCRATCH_TOTAL (O_WCB + N_WCATB)

__device__ __align__(16) float g_scratch[SCRATCH_TOTAL];

// ---------------- helpers ----------------
__device__ __forceinline__ float sigf(float x) { return 1.0f / (1.0f + __expf(-x)); }
__device__ __forceinline__ float tanh_ap(float x) {
    float y;
    asm("tanh.approx.f32 %0, %1;" : "=f"(y) : "f"(x));
    return y;
}
typedef unsigned long long ull;
__device__ __forceinline__ ull pack2(float x, float y) {
    ull r; asm("mov.b64 %0, {%1, %2};" : "=l"(r) : "f"(x), "f"(y)); return r;
}
__device__ __forceinline__ float2 unpack2(ull v) {
    float2 f; asm("mov.b64 {%0, %1}, %2;" : "=f"(f.x), "=f"(f.y) : "l"(v)); return f;
}
__device__ __forceinline__ ull fma2(ull a, ull b, ull c) {
    ull d; asm("fma.rn.f32x2 %0, %1, %2, %3;" : "=l"(d) : "l"(a), "l"(b), "l"(c)); return d;
}
// expand packed bf16 pair (lo,hi halves of u32) to f32x2
__device__ __forceinline__ ull bf2(unsigned v) {
    return pack2(__uint_as_float(v << 16), __uint_as_float(v & 0xFFFF0000u));
}

// ---------------- GEMM: C[M,N] = A[M,K] @ W[N, wcol0:wcol0+K]^T (+ bias) ----------------
// Double-buffered smem, one __syncthreads per k-octet; register prefetch.
__global__ __launch_bounds__(256, 2) void gemm_bias(
    const float* __restrict__ A, const float* __restrict__ W,
    const float* __restrict__ bias, float* __restrict__ C,
    int M, int N, int K, int ldw, int wcol0, int hasBias)
{
    __shared__ float As[2][8][132];
    __shared__ float Ws[2][8][132];
    int bm = blockIdx.y, bn = blockIdx.x;
    int tid = threadIdx.x;
    int tm = tid >> 4, tn = tid & 15;

    int lrow = tid >> 1;
    int kq   = (tid & 1) * 4;

    const float* Ag = A + (long long)(bm * 128 + lrow) * K + kq;
    const float* Wg = W + (long long)(bn * 128 + lrow) * ldw + wcol0 + kq;

    float acc[8][8];
#pragma unroll
    for (int i = 0; i < 8; i++)
#pragma unroll
        for (int j = 0; j < 8; j++) acc[i][j] = 0.0f;

    // preload + stage octet 0 into buffer 0
    float4 av = *(const float4*)Ag;
    float4 wv = *(const float4*)Wg;
    As[0][kq + 0][lrow] = av.x; As[0][kq + 1][lrow] = av.y;
    As[0][kq + 2][lrow] = av.z; As[0][kq + 3][lrow] = av.w;
    Ws[0][kq + 0][lrow] = wv.x; Ws[0][kq + 1][lrow] = wv.y;
    Ws[0][kq + 2][lrow] = wv.z; Ws[0][kq + 3][lrow] = wv.w;

    int nOct = K >> 3;
    for (int it = 0; it < nOct; it++) {
        __syncthreads();
        int cur = it & 1;
        if (it + 1 < nOct) {
            av = *(const float4*)(Ag + (it + 1) * 8);
            wv = *(const float4*)(Wg + (it + 1) * 8);
        }
#pragma unroll
        for (int kk = 0; kk < 8; kk++) {
            float4 a0 = *(const float4*)&As[cur][kk][tm * 8];
            float4 a1 = *(const float4*)&As[cur][kk][tm * 8 + 4];
            float4 b0 = *(const float4*)&Ws[cur][kk][tn * 8];
            float4 b1 = *(const float4*)&Ws[cur][kk][tn * 8 + 4];
            float ar[8] = {a0.x, a0.y, a0.z, a0.w, a1.x, a1.y, a1.z, a1.w};
            float br[8] = {b0.x, b0.y, b0.z, b0.w, b1.x, b1.y, b1.z, b1.w};
#pragma unroll
            for (int i = 0; i < 8; i++)
#pragma unroll
                for (int j = 0; j < 8; j++) acc[i][j] += ar[i] * br[j];
        }
        if (it + 1 < nOct) {
            int nxt = cur ^ 1;
            As[nxt][kq + 0][lrow] = av.x; As[nxt][kq + 1][lrow] = av.y;
            As[nxt][kq + 2][lrow] = av.z; As[nxt][kq + 3][lrow] = av.w;
            Ws[nxt][kq + 0][lrow] = wv.x; Ws[nxt][kq + 1][lrow] = wv.y;
            Ws[nxt][kq + 2][lrow] = wv.z; Ws[nxt][kq + 3][lrow] = wv.w;
        }
    }

    float bv[8];
#pragma unroll
    for (int j = 0; j < 8; j++)
        bv[j] = hasBias ? bias[bn * 128 + tn * 8 + j] : 0.0f;

#pragma unroll
    for (int i = 0; i < 8; i++) {
        long long crow = (long long)(bm * 128 + tm * 8 + i) * N + bn * 128 + tn * 8;
        float4 s0 = make_float4(acc[i][0] + bv[0], acc[i][1] + bv[1], acc[i][2] + bv[2], acc[i][3] + bv[3]);
        float4 s1 = make_float4(acc[i][4] + bv[4], acc[i][5] + bv[5], acc[i][6] + bv[6], acc[i][7] + bv[7]);
        *(float4*)(C + crow) = s0;
        *(float4*)(C + crow + 4) = s1;
    }
}

// ---------------- weight pack for match scan (k-blocked layout) ----------------
// WcatB[(kc*384 + c)*4 + j] = bf16 pair of cols (2c, 2c+1) at k = 4*kc + j.
__global__ void make_wcatb(const float* __restrict__ Wh,
                           const float* __restrict__ Whh,
                           unsigned* __restrict__ out)
{
    int i = blockIdx.x * 256 + threadIdx.x;
    if (i >= 128 * 384) return;
    int k = i / 384, c = i % 384;
    int c0 = 2 * c, c1 = 2 * c + 1;
    float w0 = (c0 < 256) ? Wh[c0 * 128 + k] : Whh[(c0 - 256) * 128 + k];
    float w1 = (c1 < 256) ? Wh[c1 * 128 + k] : Whh[(c1 - 256) * 128 + k];
    unsigned lo = (unsigned)__bfloat16_as_ushort(__float2bfloat16(w0));
    unsigned hi = (unsigned)__bfloat16_as_ushort(__float2bfloat16(w1));
    int kc = k >> 2, j = k & 3;
    out[(kc * 384 + c) * 4 + j] = lo | (hi << 16);
}

// ---------------- pre-BiLSTM scan (one direction per CTA, X prefetch) ----------------
__global__ __launch_bounds__(384, 1) void pre_scan(
    const float* __restrict__ X, const float* __restrict__ mask,
    const float* __restrict__ Whh, float* __restrict__ Hout, int T)
{
    __shared__ __align__(16) float h_s[128];
    __shared__ __align__(16) float c_s[128];
    __shared__ float gates[384];
    int b = blockIdx.x & 63;
    int d = blockIdx.x >> 6;
    int j = threadIdx.x;

    float4 w[32];
    const float4* wrow = (const float4*)(Whh + j * 128);
#pragma unroll
    for (int i = 0; i < 32; i++) w[i] = wrow[i];

    if (j < 128) { h_s[j] = 0.f; c_s[j] = 0.f; }
    __syncthreads();

    // prefetch step-0 input
    float xin = X[((long long)(d ? (T - 1) : 0) * BATCH + b) * 384 + j];

    for (int t = 0; t < T; t++) {
        int td = d ? (T - 1 - t) : t;
        float acc = xin;
        if (t + 1 < T) {
            int tdn = d ? (T - 2 - t) : (t + 1);
            xin = X[((long long)tdn * BATCH + b) * 384 + j];
        }
        const float4* h0 = (const float4*)h_s;
#pragma unroll 8
        for (int i = 0; i < 32; i++) {
            float4 x0 = h0[i];
            acc += w[i].x * x0.x + w[i].y * x0.y + w[i].z * x0.z + w[i].w * x0.w;
        }
        gates[j] = acc;
        __syncthreads();
        if (j < 128) {
            float ig = gates[j], fg = gates[128 + j], gg = gates[256 + j];
            float m = mask[td * BATCH + b];
            float c2 = (sigf(fg) * c_s[j] + sigf(ig) * tanhf(gg)) * m;
            float h2 = tanhf(c2);
            c_s[j] = c2;
            h_s[j] = h2;
            Hout[((long long)td * BATCH + b) * 256 + d * 128 + j] = h2;
        }
        __syncthreads();
    }
}

// ---------------- Match-LSTM scan (v6: k-blocked LDG.128 weights, init prefetch) ----------------
// grid = 128 (b = bx&63, d = bx>>6), block = 512.
#define MS_YQ    0                       // 60*512
#define MS_AQ    (MS_YQ + 60 * 512)      // 60*256
#define MS_WA    (MS_AQ + 60 * 256)      // 256
#define MS_U     (MS_WA + 256)           // 256
#define MS_G     (MS_U + 256)            // 512
#define MS_HS    (MS_G + 512)            // 128  (plain h floats)
#define MS_AL    (MS_HS + 128)           // 64   (scalar logits)
#define MS_AL2   (MS_AL + 64)            // 128  (64 ull splatted alphas)
#define MS_TOTAL (MS_AL2 + 128)
#define MATCH_SMEM_BYTES (MS_TOTAL * 4)

__global__ __launch_bounds__(512, 1) void match_scan(
    const float* __restrict__ ap,       // [600,64,256]
    const float* __restrict__ xp,       // [600,64,512]
    const float* __restrict__ aq,       // [60,64,256]
    const float* __restrict__ Yq,       // [60,64,512]
    const unsigned* __restrict__ WcatB, // k-blocked bf16 pairs
    const float* __restrict__ Wa,       // [256]
    const float* __restrict__ ba,       // [1]
    const float* __restrict__ mask,     // [600,64]
    float* __restrict__ out)            // [600,64,256]
{
    extern __shared__ __align__(16) float sm[];
    float* Yq_s = sm + MS_YQ;
    float* aq_s = sm + MS_AQ;
    float* Wa_s = sm + MS_WA;
    float* u_s  = sm + MS_U;
    float* g_s  = sm + MS_G;
    float* h_s  = sm + MS_HS;
    float* al_s = sm + MS_AL;
    ull*   al2  = (ull*)(sm + MS_AL2);

    int b = blockIdx.x & 63;
    int d = blockIdx.x >> 6;
    int tid = threadIdx.x;
    int lane = tid & 31;

    // stage per-batch tensors to smem
    for (int idx = tid; idx < 60 * 128; idx += 512) {
        int tq = idx >> 7, jj = idx & 127;
        ((float4*)Yq_s)[idx] = *(const float4*)(Yq + ((long long)tq * BATCH + b) * 512 + jj * 4);
    }
    for (int idx = tid; idx < 60 * 64; idx += 512) {
        int tq = idx >> 6, jj = idx & 63;
        ((float4*)aq_s)[idx] = *(const float4*)(aq + ((long long)tq * BATCH + b) * 256 + jj * 4);
    }
    if (tid < 256) Wa_s[tid] = Wa[tid];
    if (tid < 128) h_s[tid] = 0.f;
    float bav = ba[0];
    float c_reg = 0.f;   // cell state for tid<128 (unit k = tid)
    __syncthreads();

    // prefetch step-0 init (ap for u-cols, xp for gate-cols)
    float2 initv = make_float2(0.f, 0.f);
    {
        int td0 = d ? (TPLEN - 1) : 0;
        if (tid < 128)
            initv = *(const float2*)(ap + ((long long)td0 * BATCH + b) * 256 + 2 * tid);
        else if (tid < 384)
            initv = *(const float2*)(xp + ((long long)td0 * BATCH + b) * 512 + 2 * (tid - 128));
    }

    for (int t = 0; t < TPLEN; t++) {
        int td = d ? (TPLEN - 1 - t) : t;

        // ---- Phase A: [u | gates](768 cols) = init + h @ Wcat; k-blocked LDG.128
        ull acc = 0;
        if (tid < 384) {
            int cp = tid;
            ull a0 = pack2(initv.x, initv.y);
            ull a1 = pack2(0.f, 0.f);
            // prefetch next step's init while weights stream
            if (t + 1 < TPLEN) {
                int tdn = d ? (TPLEN - 2 - t) : (t + 1);
                if (cp < 128)
                    initv = *(const float2*)(ap + ((long long)tdn * BATCH + b) * 256 + 2 * cp);
                else
                    initv = *(const float2*)(xp + ((long long)tdn * BATCH + b) * 512 + 2 * (cp - 128));
            }
            const uint4* wp = (const uint4*)WcatB + cp;
            const float4* hp4 = (const float4*)h_s;
#pragma unroll 8
            for (int kc = 0; kc < 32; kc++) {
                uint4 w4 = wp[kc * 384];
                float4 hv = hp4[kc];
                a0 = fma2(bf2(w4.x), pack2(hv.x, hv.x), a0);
                a1 = fma2(bf2(w4.y), pack2(hv.y, hv.y), a1);
                a0 = fma2(bf2(w4.z), pack2(hv.z, hv.z), a0);
                a1 = fma2(bf2(w4.w), pack2(hv.w, hv.w), a1);
            }
            float2 f0 = unpack2(a0), f1 = unpack2(a1);
            f0.x += f1.x; f0.y += f1.y;
            acc = pack2(f0.x, f0.y);
            if (cp < 128) *(float2*)&u_s[2 * cp] = f0;
        }
        __syncthreads();

        // ---- Phase 2: logits e[tq] = ba + sum_i Wa[i]*tanh(aq[tq,i] + u[i])
        {
            int tq = tid >> 3, l8 = tid & 7;
            if (tq < TQLEN) {
                const float* aqr = aq_s + tq * 256;
                float a0 = 0.f;
#pragma unroll
                for (int ii = 0; ii < 32; ii++) {
                    int i = l8 * 32 + ((ii + lane) & 31);  // bank-stagger
                    a0 += Wa_s[i] * tanh_ap(aqr[i] + u_s[i]);
                }
                a0 += __shfl_xor_sync(0xffffffffu, a0, 1);
                a0 += __shfl_xor_sync(0xffffffffu, a0, 2);
                a0 += __shfl_xor_sync(0xffffffffu, a0, 4);
                if (l8 == 0) al_s[tq] = a0 + bav;
            }
        }
        __syncthreads();

        // ---- Phase 3: softmax over TQ (warp 0), write splatted alphas
        if (tid < 32) {
            float e0 = (lane < TQLEN) ? al_s[lane] : -1e30f;
            float e1 = (lane + 32 < TQLEN) ? al_s[lane + 32] : -1e30f;
            float mx = fmaxf(e0, e1);
#pragma unroll
            for (int o = 16; o; o >>= 1) mx = fmaxf(mx, __shfl_xor_sync(0xffffffffu, mx, o));
            float s0 = (lane < TQLEN) ? __expf(e0 - mx) : 0.f;
            float s1 = (lane + 32 < TQLEN) ? __expf(e1 - mx) : 0.f;
            float s = s0 + s1;
#pragma unroll
            for (int o = 16; o; o >>= 1) s += __shfl_xor_sync(0xffffffffu, s, o);
            float inv = 1.0f / s;
            if (lane < TQLEN) { float v = s0 * inv; al2[lane] = pack2(v, v); }
            if (lane + 32 < TQLEN) { float v = s1 * inv; al2[lane + 32] = pack2(v, v); }
        }
        __syncthreads();

        // ---- Phase 4: gates += sum_tq alpha[tq] * Yq[tq]; dual accumulators
        if (tid >= 128 && tid < 384) {
            int gp = tid - 128;  // gate col pair (2gp, 2gp+1)
            const ull* yq2 = (const ull*)Yq_s + gp;
            ull a0 = acc;
            ull a1 = pack2(0.f, 0.f);
#pragma unroll 4
            for (int tq = 0; tq < TQLEN; tq += 2) {
                a0 = fma2(al2[tq],     yq2[tq * 256],       a0);
                a1 = fma2(al2[tq + 1], yq2[(tq + 1) * 256], a1);
            }
            float2 f0 = unpack2(a0), f1 = unpack2(a1);
            f0.x += f1.x; f0.y += f1.y;
            *(float2*)&g_s[2 * gp] = f0;
        }
        __syncthreads();

        // ---- Phase 5: LSTM cell (c in registers), write h + output
        if (tid < 128) {
            int k = tid;
            float ig = g_s[k], fg = g_s[128 + k], gg = g_s[256 + k], og = g_s[384 + k];
            float m = mask[td * BATCH + b];
            float c2 = sigf(fg) * c_reg + sigf(ig) * tanhf(gg);
            float h2 = sigf(og) * tanhf(c2);
            c2 *= m; h2 *= m;
            c_reg = c2;
            h_s[k] = h2;
            out[((long long)td * BATCH + b) * 256 + d * 128 + k] = h2;
        }
        __syncthreads();
    }
}

// ---------------- host ----------------
static void launch_gemm(const float* A, const float* W, const float* bias, float* C,
                        int M, int N, int K, int ldw, int wcol0)
{
    dim3 g(N / 128, M / 128);
    gemm_bias<<<g, 256>>>(A, W, bias, C, M, N, K, ldw, wcol0, bias != nullptr ? 1 : 0);
}

extern "C" void kernel_launch(void* const* d_in, const int* in_sizes, int n_in,
                              void* d_out, int out_size)
{
    const float* passage  = (const float*)d_in[0];
    const float* question = (const float*)d_in[1];
    const float* mask_p   = (const float*)d_in[2];
    const float* mask_q   = (const float*)d_in[3];
    const float* pre0_Wih = (const float*)d_in[4];
    const float* pre0_Whh = (const float*)d_in[5];
    const float* pre0_b   = (const float*)d_in[6];
    const float* pre1_Wih = (const float*)d_in[7];
    const float* pre1_Whh = (const float*)d_in[8];
    const float* pre1_b   = (const float*)d_in[9];
    const float* mq_Wq    = (const float*)d_in[10];
    const float* mq_Wp    = (const float*)d_in[11];
    const float* mq_bp    = (const float*)d_in[12];
    const float* mq_Wh    = (const float*)d_in[13];
    const float* mq_Wa    = (const float*)d_in[14];
    const float* mq_ba    = (const float*)d_in[15];
    const float* mq_Wih   = (const float*)d_in[16];
    const float* mq_Whh   = (const float*)d_in[17];
    const float* mq_b     = (const float*)d_in[18];
    float* out = (float*)d_out;

    float* s = nullptr;
    cudaGetSymbolAddress((void**)&s, g_scratch);

    float* X0p = s + O_X0p;
    float* X0q = s + O_X0q;
    float* Hp0 = s + O_Hp0;
    float* Hq0 = s + O_Hq0;
    float* Hp1 = s + O_Hp1;
    float* Hq1 = s + O_Hq1;
    float* aqb = s + O_aq;
    float* apb = s + O_ap;
    float* xpb = s + O_xp;
    float* Yqb = s + O_Yq;
    unsigned* WcatB = (unsigned*)(s + O_WCB);

    cudaFuncSetAttribute(match_scan, cudaFuncAttributeMaxDynamicSharedMemorySize,
                         MATCH_SMEM_BYTES);

    // bf16 weight pack for the match scan (independent of data path)
    make_wcatb<<<(128 * 384 + 255) / 256, 256>>>(mq_Wh, mq_Whh, WcatB);

    // ---- pre layer 0 (i,f,g gates only: 384 rows) ----
    launch_gemm(passage,  pre0_Wih, pre0_b, X0p, TPLEN * BATCH, 384, 344, 344, 0);
    launch_gemm(question, pre0_Wih, pre0_b, X0q, TQLEN * BATCH, 384, 344, 344, 0);
    pre_scan<<<2 * BATCH, 384>>>(X0p, mask_p, pre0_Whh, Hp0, TPLEN);
    pre_scan<<<2 * BATCH, 384>>>(X0q, mask_q, pre0_Whh, Hq0, TQLEN);

    // ---- pre layer 1 ----
    launch_gemm(Hp0, pre1_Wih, pre1_b, X0p, TPLEN * BATCH, 384, 256, 256, 0);
    launch_gemm(Hq0, pre1_Wih, pre1_b, X0q, TQLEN * BATCH, 384, 256, 256, 0);
    pre_scan<<<2 * BATCH, 384>>>(X0p, mask_p, pre1_Whh, Hp1, TPLEN);
    pre_scan<<<2 * BATCH, 384>>>(X0q, mask_q, pre1_Whh, Hq1, TQLEN);

    // ---- match precompute ----
    launch_gemm(Hq1, mq_Wq, nullptr, aqb, TQLEN * BATCH, 256, 256, 256, 0);
    launch_gemm(Hp1, mq_Wp, mq_bp,   apb, TPLEN * BATCH, 256, 256, 256, 0);
    launch_gemm(Hp1, mq_Wih, mq_b,   xpb, TPLEN * BATCH, 512, 256, 512, 0);
    launch_gemm(Hq1, mq_Wih, nullptr, Yqb, TQLEN * BATCH, 512, 256, 512, 256);

    // ---- match scan ----
    match_scan<<<2 * BATCH, 512, MATCH_SMEM_BYTES>>>(
        apb, xpb, aqb, Yqb, WcatB, mq_Wa, mq_ba, mask_p, out);

    (void)in_sizes; (void)n_in; (void)out_size;
}

// round 11
// speedup vs baseline: 1.3231x; 1.0902x over previous
#include <cuda_runtime.h>
#include <cuda_bf16.h>
#include <math.h>
#include <stdint.h>

// ---------------- problem constants ----------------
#define TPLEN 600
#define TQLEN 60
#define BATCH 64
// H=256, H2=128, EMB=344

// ---------------- scratch ----------------
#define N_XP   (600LL*64*384)
#define N_XQ   (60LL*64*384)
#define N_HP   (600LL*64*256)
#define N_HQ   (60LL*64*256)
#define N_XPM  (600LL*64*512)
#define N_YQ   (60LL*64*512)
#define N_WCATB (128LL*384)          // u32 elements (bf16 pairs), k-blocked layout

#define O_X0p  0LL
#define O_X0q  (O_X0p + N_XP)
#define O_Hp0  (O_X0q + N_XQ)
#define O_Hq0  (O_Hp0 + N_HP)
#define O_Hp1  (O_Hq0 + N_HQ)
#define O_Hq1  (O_Hp1 + N_HP)
#define O_aq   (O_Hq1 + N_HQ)
#define O_ap   (O_aq  + N_HQ)
#define O_xp   (O_ap  + N_HP)
#define O_Yq   (O_xp  + N_XPM)
#define O_WCB  (O_Yq  + N_YQ)
#define SCRATCH_TOTAL (O_WCB + N_WCATB)

__device__ __align__(16) float g_scratch[SCRATCH_TOTAL];

// ---------------- helpers ----------------
__device__ __forceinline__ float sigf(float x) { return 1.0f / (1.0f + __expf(-x)); }
__device__ __forceinline__ float tanh_ap(float x) {
    float y;
    asm("tanh.approx.f32 %0, %1;" : "=f"(y) : "f"(x));
    return y;
}
typedef unsigned long long ull;
__device__ __forceinline__ ull pack2(float x, float y) {
    ull r; asm("mov.b64 %0, {%1, %2};" : "=l"(r) : "f"(x), "f"(y)); return r;
}
__device__ __forceinline__ float2 unpack2(ull v) {
    float2 f; asm("mov.b64 {%0, %1}, %2;" : "=f"(f.x), "=f"(f.y) : "l"(v)); return f;
}
__device__ __forceinline__ ull fma2(ull a, ull b, ull c) {
    ull d; asm("fma.rn.f32x2 %0, %1, %2, %3;" : "=l"(d) : "l"(a), "l"(b), "l"(c)); return d;
}
// expand packed bf16 pair (lo,hi halves of u32) to f32x2
__device__ __forceinline__ ull bf2(unsigned v) {
    return pack2(__uint_as_float(v << 16), __uint_as_float(v & 0xFFFF0000u));
}

// ---------------- GEMM: C[M,N] = A[M,K] @ W[N, wcol0:wcol0+K]^T (+ bias) ----------------
// Double-buffered smem, one __syncthreads per k-octet; register prefetch.
__global__ __launch_bounds__(256, 2) void gemm_bias(
    const float* __restrict__ A, const float* __restrict__ W,
    const float* __restrict__ bias, float* __restrict__ C,
    int M, int N, int K, int ldw, int wcol0, int hasBias)
{
    __shared__ float As[2][8][132];
    __shared__ float Ws[2][8][132];
    int bm = blockIdx.y, bn = blockIdx.x;
    int tid = threadIdx.x;
    int tm = tid >> 4, tn = tid & 15;

    int lrow = tid >> 1;
    int kq   = (tid & 1) * 4;

    const float* Ag = A + (long long)(bm * 128 + lrow) * K + kq;
    const float* Wg = W + (long long)(bn * 128 + lrow) * ldw + wcol0 + kq;

    float acc[8][8];
#pragma unroll
    for (int i = 0; i < 8; i++)
#pragma unroll
        for (int j = 0; j < 8; j++) acc[i][j] = 0.0f;

    float4 av = *(const float4*)Ag;
    float4 wv = *(const float4*)Wg;
    As[0][kq + 0][lrow] = av.x; As[0][kq + 1][lrow] = av.y;
    As[0][kq + 2][lrow] = av.z; As[0][kq + 3][lrow] = av.w;
    Ws[0][kq + 0][lrow] = wv.x; Ws[0][kq + 1][lrow] = wv.y;
    Ws[0][kq + 2][lrow] = wv.z; Ws[0][kq + 3][lrow] = wv.w;

    int nOct = K >> 3;
    for (int it = 0; it < nOct; it++) {
        __syncthreads();
        int cur = it & 1;
        if (it + 1 < nOct) {
            av = *(const float4*)(Ag + (it + 1) * 8);
            wv = *(const float4*)(Wg + (it + 1) * 8);
        }
#pragma unroll
        for (int kk = 0; kk < 8; kk++) {
            float4 a0 = *(const float4*)&As[cur][kk][tm * 8];
            float4 a1 = *(const float4*)&As[cur][kk][tm * 8 + 4];
            float4 b0 = *(const float4*)&Ws[cur][kk][tn * 8];
            float4 b1 = *(const float4*)&Ws[cur][kk][tn * 8 + 4];
            float ar[8] = {a0.x, a0.y, a0.z, a0.w, a1.x, a1.y, a1.z, a1.w};
            float br[8] = {b0.x, b0.y, b0.z, b0.w, b1.x, b1.y, b1.z, b1.w};
#pragma unroll
            for (int i = 0; i < 8; i++)
#pragma unroll
                for (int j = 0; j < 8; j++) acc[i][j] += ar[i] * br[j];
        }
        if (it + 1 < nOct) {
            int nxt = cur ^ 1;
            As[nxt][kq + 0][lrow] = av.x; As[nxt][kq + 1][lrow] = av.y;
            As[nxt][kq + 2][lrow] = av.z; As[nxt][kq + 3][lrow] = av.w;
            Ws[nxt][kq + 0][lrow] = wv.x; Ws[nxt][kq + 1][lrow] = wv.y;
            Ws[nxt][kq + 2][lrow] = wv.z; Ws[nxt][kq + 3][lrow] = wv.w;
        }
    }

    float bv[8];
#pragma unroll
    for (int j = 0; j < 8; j++)
        bv[j] = hasBias ? bias[bn * 128 + tn * 8 + j] : 0.0f;

#pragma unroll
    for (int i = 0; i < 8; i++) {
        long long crow = (long long)(bm * 128 + tm * 8 + i) * N + bn * 128 + tn * 8;
        float4 s0 = make_float4(acc[i][0] + bv[0], acc[i][1] + bv[1], acc[i][2] + bv[2], acc[i][3] + bv[3]);
        float4 s1 = make_float4(acc[i][4] + bv[4], acc[i][5] + bv[5], acc[i][6] + bv[6], acc[i][7] + bv[7]);
        *(float4*)(C + crow) = s0;
        *(float4*)(C + crow + 4) = s1;
    }
}

// ---------------- weight pack for match scan (k-blocked layout) ----------------
// WcatB[(kc*384 + c)*4 + j] = bf16 pair of cols (2c, 2c+1) at k = 4*kc + j.
__global__ void make_wcatb(const float* __restrict__ Wh,
                           const float* __restrict__ Whh,
                           unsigned* __restrict__ out)
{
    int i = blockIdx.x * 256 + threadIdx.x;
    if (i >= 128 * 384) return;
    int k = i / 384, c = i % 384;
    int c0 = 2 * c, c1 = 2 * c + 1;
    float w0 = (c0 < 256) ? Wh[c0 * 128 + k] : Whh[(c0 - 256) * 128 + k];
    float w1 = (c1 < 256) ? Wh[c1 * 128 + k] : Whh[(c1 - 256) * 128 + k];
    unsigned lo = (unsigned)__bfloat16_as_ushort(__float2bfloat16(w0));
    unsigned hi = (unsigned)__bfloat16_as_ushort(__float2bfloat16(w1));
    int kc = k >> 2, j = k & 3;
    out[(kc * 384 + c) * 4 + j] = lo | (hi << 16);
}

// ---------------- fused pre-BiLSTM scan (passage + question, one direction per CTA) ----------------
// grid = 256: bx<128 -> passage (b=bx&63, d=bx>>6, T=600); bx>=128 -> question (T=60).
__global__ __launch_bounds__(384, 1) void pre_scan_fused(
    const float* __restrict__ Xp, const float* __restrict__ Xq,
    const float* __restrict__ mask_p, const float* __restrict__ mask_q,
    const float* __restrict__ Whh,
    float* __restrict__ Hp, float* __restrict__ Hq)
{
    __shared__ __align__(16) float h_s[128];
    __shared__ __align__(16) float c_s[128];
    __shared__ float gates[384];
    int bx = blockIdx.x;
    const float* X; const float* mask; float* Hout; int T, b, d;
    if (bx < 128) { X = Xp; mask = mask_p; Hout = Hp; T = TPLEN; b = bx & 63; d = bx >> 6; }
    else { int v = bx - 128; X = Xq; mask = mask_q; Hout = Hq; T = TQLEN; b = v & 63; d = v >> 6; }
    int j = threadIdx.x;

    float4 w[32];
    const float4* wrow = (const float4*)(Whh + j * 128);
#pragma unroll
    for (int i = 0; i < 32; i++) w[i] = wrow[i];

    if (j < 128) { h_s[j] = 0.f; c_s[j] = 0.f; }
    __syncthreads();

    float xin = X[((long long)(d ? (T - 1) : 0) * BATCH + b) * 384 + j];

    for (int t = 0; t < T; t++) {
        int td = d ? (T - 1 - t) : t;
        float acc = xin;
        if (t + 1 < T) {
            int tdn = d ? (T - 2 - t) : (t + 1);
            xin = X[((long long)tdn * BATCH + b) * 384 + j];
        }
        const float4* h0 = (const float4*)h_s;
#pragma unroll 8
        for (int i = 0; i < 32; i++) {
            float4 x0 = h0[i];
            acc += w[i].x * x0.x + w[i].y * x0.y + w[i].z * x0.z + w[i].w * x0.w;
        }
        gates[j] = acc;
        __syncthreads();
        if (j < 128) {
            float ig = gates[j], fg = gates[128 + j], gg = gates[256 + j];
            float m = mask[td * BATCH + b];
            float c2 = (sigf(fg) * c_s[j] + sigf(ig) * tanhf(gg)) * m;
            float h2 = tanhf(c2);
            c_s[j] = c2;
            h_s[j] = h2;
            Hout[((long long)td * BATCH + b) * 256 + d * 128 + j] = h2;
        }
        __syncthreads();
    }
}

// ---------------- Match-LSTM scan (v7: smem weight cache + Yq in registers) ----------------
// grid = 128 (b = bx&63, d = bx>>6), block = 512.
// Yq held in registers: thread pair (gp = tid>>1, half = tid&1) holds 30 ull each.
// Weights: k-chunks 0..25 cached in smem (staged once); 26..31 from L2.
#define NCKC 26                         // cached k-chunks (of 32)
#define MS_AQ    0                       // 60*256
#define MS_WA    (MS_AQ + 60 * 256)      // 256
#define MS_U     (MS_WA + 256)           // 256
#define MS_G     (MS_U + 256)            // 512 (floats; aliased as 256 ull partials)
#define MS_HS    (MS_G + 512)            // 256  (128 ull h-splats)
#define MS_AL    (MS_HS + 256)           // 64   (scalar logits)
#define MS_AL2   (MS_AL + 64)            // 128  (64 ull splatted alphas)
#define MS_WC    (MS_AL2 + 128)          // NCKC*384*4 u32 weight cache
#define MS_TOTAL (MS_WC + NCKC * 384 * 4)
#define MATCH_SMEM_BYTES (MS_TOTAL * 4)

__global__ __launch_bounds__(512, 1) void match_scan(
    const float* __restrict__ ap,       // [600,64,256]
    const float* __restrict__ xp,       // [600,64,512]
    const float* __restrict__ aq,       // [60,64,256]
    const float* __restrict__ Yq,       // [60,64,512]
    const unsigned* __restrict__ WcatB, // k-blocked bf16 pairs
    const float* __restrict__ Wa,       // [256]
    const float* __restrict__ ba,       // [1]
    const float* __restrict__ mask,     // [600,64]
    float* __restrict__ out)            // [600,64,256]
{
    extern __shared__ __align__(16) float sm[];
    float* aq_s = sm + MS_AQ;
    float* Wa_s = sm + MS_WA;
    float* u_s  = sm + MS_U;
    float* g_s  = sm + MS_G;
    ull*   g2u  = (ull*)g_s;
    ull*   hsp  = (ull*)(sm + MS_HS);
    float* al_s = sm + MS_AL;
    ull*   al2  = (ull*)(sm + MS_AL2);
    unsigned* Wc = (unsigned*)(sm + MS_WC);

    int b = blockIdx.x & 63;
    int d = blockIdx.x >> 6;
    int tid = threadIdx.x;
    int lane = tid & 31;
    int gp = tid >> 1, half = tid & 1;

    // ---- stage weight cache (26 k-chunks, 160KB)
    for (int idx = tid; idx < NCKC * 384; idx += 512)
        ((uint4*)Wc)[idx] = ((const uint4*)WcatB)[idx];

    // ---- stage aq
    for (int idx = tid; idx < 60 * 64; idx += 512) {
        int tq = idx >> 6, jj = idx & 63;
        ((float4*)aq_s)[idx] = *(const float4*)(aq + ((long long)tq * BATCH + b) * 256 + jj * 4);
    }
    if (tid < 256) Wa_s[tid] = Wa[tid];
    if (tid < 128) hsp[tid] = 0ull;
    float bav = ba[0];
    float c_reg = 0.f;   // cell state for tid<128 (unit k = tid)

    // ---- Yq into registers: thread (gp, half) holds tq = half*30 .. half*30+29
    ull yqr[30];
#pragma unroll
    for (int i = 0; i < 30; i++)
        yqr[i] = *((const ull*)(Yq + ((long long)(half * 30 + i) * BATCH + b) * 512) + gp);

    __syncthreads();

    // prefetch step-0 init (ap for u-cols, xp for gate-cols)
    float2 initv = make_float2(0.f, 0.f);
    {
        int td0 = d ? (TPLEN - 1) : 0;
        if (tid < 128)
            initv = *(const float2*)(ap + ((long long)td0 * BATCH + b) * 256 + 2 * tid);
        else if (tid < 384)
            initv = *(const float2*)(xp + ((long long)td0 * BATCH + b) * 512 + 2 * (tid - 128));
    }

    for (int t = 0; t < TPLEN; t++) {
        int td = d ? (TPLEN - 1 - t) : t;

        // ---- Phase A: [u | gates](768 cols) = init + h @ Wcat
        if (tid < 384) {
            int cp = tid;
            const uint4* wg = (const uint4*)WcatB + cp;
            // issue residual global weight loads early
            uint4 w26 = wg[26 * 384];
            uint4 w27 = wg[27 * 384];
            uint4 w28 = wg[28 * 384];
            uint4 w29 = wg[29 * 384];
            uint4 w30 = wg[30 * 384];
            uint4 w31 = wg[31 * 384];
            ull a0 = pack2(initv.x, initv.y);
            ull a1 = pack2(0.f, 0.f);
            // prefetch next step's init while weights stream
            if (t + 1 < TPLEN) {
                int tdn = d ? (TPLEN - 2 - t) : (t + 1);
                if (cp < 128)
                    initv = *(const float2*)(ap + ((long long)tdn * BATCH + b) * 256 + 2 * cp);
                else
                    initv = *(const float2*)(xp + ((long long)tdn * BATCH + b) * 512 + 2 * (cp - 128));
            }
            const ulonglong2* hp2 = (const ulonglong2*)hsp;
#pragma unroll 13
            for (int kc = 0; kc < NCKC; kc++) {
                uint4 w4 = ((const uint4*)Wc)[kc * 384 + cp];
                ulonglong2 ha = hp2[2 * kc];
                ulonglong2 hb = hp2[2 * kc + 1];
                a0 = fma2(bf2(w4.x), ha.x, a0);
                a1 = fma2(bf2(w4.y), ha.y, a1);
                a0 = fma2(bf2(w4.z), hb.x, a0);
                a1 = fma2(bf2(w4.w), hb.y, a1);
            }
            // residual chunks from registers
            {
                ulonglong2 ha, hb;
                uint4 w4;
#define RES_CHUNK(KC, W4) \
                w4 = W4; \
                ha = hp2[2 * (KC)]; hb = hp2[2 * (KC) + 1]; \
                a0 = fma2(bf2(w4.x), ha.x, a0); \
                a1 = fma2(bf2(w4.y), ha.y, a1); \
                a0 = fma2(bf2(w4.z), hb.x, a0); \
                a1 = fma2(bf2(w4.w), hb.y, a1);
                RES_CHUNK(26, w26) RES_CHUNK(27, w27) RES_CHUNK(28, w28)
                RES_CHUNK(29, w29) RES_CHUNK(30, w30) RES_CHUNK(31, w31)
#undef RES_CHUNK
            }
            float2 f0 = unpack2(a0), f1 = unpack2(a1);
            f0.x += f1.x; f0.y += f1.y;
            if (cp < 128) *(float2*)&u_s[2 * cp] = f0;
            else          g2u[cp - 128] = pack2(f0.x, f0.y);
        }
        __syncthreads();

        // ---- Phase 2: logits e[tq] = ba + sum_i Wa[i]*tanh(aq[tq,i] + u[i])
        {
            int tq = tid >> 3, l8 = tid & 7;
            if (tq < TQLEN) {
                const float* aqr = aq_s + tq * 256;
                float a0 = 0.f;
#pragma unroll
                for (int ii = 0; ii < 32; ii++) {
                    int i = l8 * 32 + ((ii + lane) & 31);  // bank-stagger
                    a0 += Wa_s[i] * tanh_ap(aqr[i] + u_s[i]);
                }
                a0 += __shfl_xor_sync(0xffffffffu, a0, 1);
                a0 += __shfl_xor_sync(0xffffffffu, a0, 2);
                a0 += __shfl_xor_sync(0xffffffffu, a0, 4);
                if (l8 == 0) al_s[tq] = a0 + bav;
            }
        }
        __syncthreads();

        // ---- Phase 3: softmax over TQ (warp 0), write splatted alphas
        if (tid < 32) {
            float e0 = (lane < TQLEN) ? al_s[lane] : -1e30f;
            float e1 = (lane + 32 < TQLEN) ? al_s[lane + 32] : -1e30f;
            float mx = fmaxf(e0, e1);
#pragma unroll
            for (int o = 16; o; o >>= 1) mx = fmaxf(mx, __shfl_xor_sync(0xffffffffu, mx, o));
            float s0 = (lane < TQLEN) ? __expf(e0 - mx) : 0.f;
            float s1 = (lane + 32 < TQLEN) ? __expf(e1 - mx) : 0.f;
            float s = s0 + s1;
#pragma unroll
            for (int o = 16; o; o >>= 1) s += __shfl_xor_sync(0xffffffffu, s, o);
            float inv = 1.0f / s;
            if (lane < TQLEN) { float v = s0 * inv; al2[lane] = pack2(v, v); }
            if (lane + 32 < TQLEN) { float v = s1 * inv; al2[lane + 32] = pack2(v, v); }
        }
        __syncthreads();

        // ---- Phase 4: gates += sum_tq alpha[tq] * Yq[tq]; Yq from registers, all 512 threads
        {
            ull a = (half == 0) ? g2u[gp] : pack2(0.f, 0.f);
#pragma unroll
            for (int i = 0; i < 30; i++)
                a = fma2(al2[half * 30 + i], yqr[i], a);
            ull other = __shfl_xor_sync(0xffffffffu, a, 1);
            if (half == 0) {
                float2 fa = unpack2(a), fo = unpack2(other);
                fa.x += fo.x; fa.y += fo.y;
                *(float2*)&g_s[2 * gp] = fa;
            }
        }
        __syncthreads();

        // ---- Phase 5: LSTM cell (c in registers), write h splats + output
        if (tid < 128) {
            int k = tid;
            float ig = g_s[k], fg = g_s[128 + k], gg = g_s[256 + k], og = g_s[384 + k];
            float m = mask[td * BATCH + b];
            float c2 = sigf(fg) * c_reg + sigf(ig) * tanhf(gg);
            float h2 = sigf(og) * tanhf(c2);
            c2 *= m; h2 *= m;
            c_reg = c2;
            hsp[k] = pack2(h2, h2);
            out[((long long)td * BATCH + b) * 256 + d * 128 + k] = h2;
        }
        __syncthreads();
    }
}

// ---------------- host ----------------
static void launch_gemm(const float* A, const float* W, const float* bias, float* C,
                        int M, int N, int K, int ldw, int wcol0)
{
    dim3 g(N / 128, M / 128);
    gemm_bias<<<g, 256>>>(A, W, bias, C, M, N, K, ldw, wcol0, bias != nullptr ? 1 : 0);
}

extern "C" void kernel_launch(void* const* d_in, const int* in_sizes, int n_in,
                              void* d_out, int out_size)
{
    const float* passage  = (const float*)d_in[0];
    const float* question = (const float*)d_in[1];
    const float* mask_p   = (const float*)d_in[2];
    const float* mask_q   = (const float*)d_in[3];
    const float* pre0_Wih = (const float*)d_in[4];
    const float* pre0_Whh = (const float*)d_in[5];
    const float* pre0_b   = (const float*)d_in[6];
    const float* pre1_Wih = (const float*)d_in[7];
    const float* pre1_Whh = (const float*)d_in[8];
    const float* pre1_b   = (const float*)d_in[9];
    const float* mq_Wq    = (const float*)d_in[10];
    const float* mq_Wp    = (const float*)d_in[11];
    const float* mq_bp    = (const float*)d_in[12];
    const float* mq_Wh    = (const float*)d_in[13];
    const float* mq_Wa    = (const float*)d_in[14];
    const float* mq_ba    = (const float*)d_in[15];
    const float* mq_Wih   = (const float*)d_in[16];
    const float* mq_Whh   = (const float*)d_in[17];
    const float* mq_b     = (const float*)d_in[18];
    float* out = (float*)d_out;

    float* s = nullptr;
    cudaGetSymbolAddress((void**)&s, g_scratch);

    float* X0p = s + O_X0p;
    float* X0q = s + O_X0q;
    float* Hp0 = s + O_Hp0;
    float* Hq0 = s + O_Hq0;
    float* Hp1 = s + O_Hp1;
    float* Hq1 = s + O_Hq1;
    float* aqb = s + O_aq;
    float* apb = s + O_ap;
    float* xpb = s + O_xp;
    float* Yqb = s + O_Yq;
    unsigned* WcatB = (unsigned*)(s + O_WCB);

    cudaFuncSetAttribute(match_scan, cudaFuncAttributeMaxDynamicSharedMemorySize,
                         MATCH_SMEM_BYTES);

    // bf16 weight pack for the match scan (independent of data path)
    make_wcatb<<<(128 * 384 + 255) / 256, 256>>>(mq_Wh, mq_Whh, WcatB);

    // ---- pre layer 0 (i,f,g gates only: 384 rows) ----
    launch_gemm(passage,  pre0_Wih, pre0_b, X0p, TPLEN * BATCH, 384, 344, 344, 0);
    launch_gemm(question, pre0_Wih, pre0_b, X0q, TQLEN * BATCH, 384, 344, 344, 0);
    pre_scan_fused<<<256, 384>>>(X0p, X0q, mask_p, mask_q, pre0_Whh, Hp0, Hq0);

    // ---- pre layer 1: Hp0/Hq0 and X0p/X0q are contiguous -> one concatenated GEMM ----
    launch_gemm(Hp0, pre1_Wih, pre1_b, X0p, (TPLEN + TQLEN) * BATCH, 384, 256, 256, 0);
    pre_scan_fused<<<256, 384>>>(X0p, X0q, mask_p, mask_q, pre1_Whh, Hp1, Hq1);

    // ---- match precompute ----
    launch_gemm(Hq1, mq_Wq, nullptr, aqb, TQLEN * BATCH, 256, 256, 256, 0);
    launch_gemm(Hp1, mq_Wp, mq_bp,   apb, TPLEN * BATCH, 256, 256, 256, 0);
    launch_gemm(Hp1, mq_Wih, mq_b,   xpb, TPLEN * BATCH, 512, 256, 512, 0);
    launch_gemm(Hq1, mq_Wih, nullptr, Yqb, TQLEN * BATCH, 512, 256, 512, 256);

    // ---- match scan ----
    match_scan<<<2 * BATCH, 512, MATCH_SMEM_BYTES>>>(
        apb, xpb, aqb, Yqb, WcatB, mq_Wa, mq_ba, mask_p, out);

    (void)in_sizes; (void)n_in; (void)out_size;
}

// round 13
// speedup vs baseline: 1.3369x; 1.0105x over previous
#include <cuda_runtime.h>
#include <cuda_bf16.h>
#include <math.h>
#include <stdint.h>

// ---------------- problem constants ----------------
#define TPLEN 600
#define TQLEN 60
#define BATCH 64
// H=256, H2=128, EMB=344

// ---------------- scratch ----------------
#define N_XP   (600LL*64*384)
#define N_XQ   (60LL*64*384)
#define N_HP   (600LL*64*256)
#define N_HQ   (60LL*64*256)
#define N_XPM  (600LL*64*512)
#define N_YQ   (60LL*64*512)
#define N_WCATB (128LL*384)          // u32 elements (bf16 pairs), k-blocked layout

#define O_X0p  0LL
#define O_X0q  (O_X0p + N_XP)
#define O_Hp0  (O_X0q + N_XQ)
#define O_Hq0  (O_Hp0 + N_HP)
#define O_Hp1  (O_Hq0 + N_HQ)
#define O_Hq1  (O_Hp1 + N_HP)
#define O_aq   (O_Hq1 + N_HQ)
#define O_ap   (O_aq  + N_HQ)
#define O_xp   (O_ap  + N_HP)
#define O_Yq   (O_xp  + N_XPM)
#define O_WCB  (O_Yq  + N_YQ)
#define SCRATCH_TOTAL (O_WCB + N_WCATB)

__device__ __align__(16) float g_scratch[SCRATCH_TOTAL];

// ---------------- helpers ----------------
__device__ __forceinline__ float sigf(float x) { return 1.0f / (1.0f + __expf(-x)); }
__device__ __forceinline__ float tanh_ap(float x) {
    float y;
    asm("tanh.approx.f32 %0, %1;" : "=f"(y) : "f"(x));
    return y;
}
typedef unsigned long long ull;
__device__ __forceinline__ ull pack2(float x, float y) {
    ull r; asm("mov.b64 %0, {%1, %2};" : "=l"(r) : "f"(x), "f"(y)); return r;
}
__device__ __forceinline__ float2 unpack2(ull v) {
    float2 f; asm("mov.b64 {%0, %1}, %2;" : "=f"(f.x), "=f"(f.y) : "l"(v)); return f;
}
__device__ __forceinline__ ull fma2(ull a, ull b, ull c) {
    ull d; asm("fma.rn.f32x2 %0, %1, %2, %3;" : "=l"(d) : "l"(a), "l"(b), "l"(c)); return d;
}
// expand packed bf16 pair (lo,hi halves of u32) to f32x2
__device__ __forceinline__ ull bf2(unsigned v) {
    return pack2(__uint_as_float(v << 16), __uint_as_float(v & 0xFFFF0000u));
}

// ---------------- GEMM: C[M,N] = A[M,K] @ W[N, wcol0:wcol0+K]^T (+ bias) ----------------
// Double-buffered smem, register prefetch, f32x2 packed FMA inner loop (full fp32).
__global__ __launch_bounds__(256, 2) void gemm_bias(
    const float* __restrict__ A, const float* __restrict__ W,
    const float* __restrict__ bias, float* __restrict__ C,
    int M, int N, int K, int ldw, int wcol0, int hasBias)
{
    __shared__ float As[2][8][132];
    __shared__ float Ws[2][8][132];
    int bm = blockIdx.y, bn = blockIdx.x;
    int tid = threadIdx.x;
    int tm = tid >> 4, tn = tid & 15;

    int lrow = tid >> 1;
    int kq   = (tid & 1) * 4;

    const float* Ag = A + (long long)(bm * 128 + lrow) * K + kq;
    const float* Wg = W + (long long)(bn * 128 + lrow) * ldw + wcol0 + kq;

    // packed accumulators: acc2[i][j] = (C[i][2j], C[i][2j+1])
    ull acc2[8][4];
#pragma unroll
    for (int i = 0; i < 8; i++)
#pragma unroll
        for (int j = 0; j < 4; j++) acc2[i][j] = pack2(0.f, 0.f);

    float4 av = *(const float4*)Ag;
    float4 wv = *(const float4*)Wg;
    As[0][kq + 0][lrow] = av.x; As[0][kq + 1][lrow] = av.y;
    As[0][kq + 2][lrow] = av.z; As[0][kq + 3][lrow] = av.w;
    Ws[0][kq + 0][lrow] = wv.x; Ws[0][kq + 1][lrow] = wv.y;
    Ws[0][kq + 2][lrow] = wv.z; Ws[0][kq + 3][lrow] = wv.w;

    int nOct = K >> 3;
    for (int it = 0; it < nOct; it++) {
        __syncthreads();
        int cur = it & 1;
        if (it + 1 < nOct) {
            av = *(const float4*)(Ag + (it + 1) * 8);
            wv = *(const float4*)(Wg + (it + 1) * 8);
        }
#pragma unroll
        for (int kk = 0; kk < 8; kk++) {
            float4 a0 = *(const float4*)&As[cur][kk][tm * 8];
            float4 a1 = *(const float4*)&As[cur][kk][tm * 8 + 4];
            const ull* bp = (const ull*)&Ws[cur][kk][tn * 8];  // 16B-aligned (132*4=528=33*16)
            ull b0 = bp[0], b1 = bp[1], b2 = bp[2], b3 = bp[3];
            float ar[8] = {a0.x, a0.y, a0.z, a0.w, a1.x, a1.y, a1.z, a1.w};
#pragma unroll
            for (int i = 0; i < 8; i++) {
                ull as = pack2(ar[i], ar[i]);
                acc2[i][0] = fma2(as, b0, acc2[i][0]);
                acc2[i][1] = fma2(as, b1, acc2[i][1]);
                acc2[i][2] = fma2(as, b2, acc2[i][2]);
                acc2[i][3] = fma2(as, b3, acc2[i][3]);
            }
        }
        if (it + 1 < nOct) {
            int nxt = cur ^ 1;
            As[nxt][kq + 0][lrow] = av.x; As[nxt][kq + 1][lrow] = av.y;
            As[nxt][kq + 2][lrow] = av.z; As[nxt][kq + 3][lrow] = av.w;
            Ws[nxt][kq + 0][lrow] = wv.x; Ws[nxt][kq + 1][lrow] = wv.y;
            Ws[nxt][kq + 2][lrow] = wv.z; Ws[nxt][kq + 3][lrow] = wv.w;
        }
    }

    float bv[8];
#pragma unroll
    for (int j = 0; j < 8; j++)
        bv[j] = hasBias ? bias[bn * 128 + tn * 8 + j] : 0.0f;

#pragma unroll
    for (int i = 0; i < 8; i++) {
        long long crow = (long long)(bm * 128 + tm * 8 + i) * N + bn * 128 + tn * 8;
        float2 c0 = unpack2(acc2[i][0]);
        float2 c1 = unpack2(acc2[i][1]);
        float2 c2 = unpack2(acc2[i][2]);
        float2 c3 = unpack2(acc2[i][3]);
        float4 s0 = make_float4(c0.x + bv[0], c0.y + bv[1], c1.x + bv[2], c1.y + bv[3]);
        float4 s1 = make_float4(c2.x + bv[4], c2.y + bv[5], c3.x + bv[6], c3.y + bv[7]);
        *(float4*)(C + crow) = s0;
        *(float4*)(C + crow + 4) = s1;
    }
}

// ---------------- weight pack for match scan (k-blocked layout) ----------------
// WcatB[(kc*384 + c)*4 + j] = bf16 pair of cols (2c, 2c+1) at k = 4*kc + j.
__global__ void make_wcatb(const float* __restrict__ Wh,
                           const float* __restrict__ Whh,
                           unsigned* __restrict__ out)
{
    int i = blockIdx.x * 256 + threadIdx.x;
    if (i >= 128 * 384) return;
    int k = i / 384, c = i % 384;
    int c0 = 2 * c, c1 = 2 * c + 1;
    float w0 = (c0 < 256) ? Wh[c0 * 128 + k] : Whh[(c0 - 256) * 128 + k];
    float w1 = (c1 < 256) ? Wh[c1 * 128 + k] : Whh[(c1 - 256) * 128 + k];
    unsigned lo = (unsigned)__bfloat16_as_ushort(__float2bfloat16(w0));
    unsigned hi = (unsigned)__bfloat16_as_ushort(__float2bfloat16(w1));
    int kc = k >> 2, j = k & 3;
    out[(kc * 384 + c) * 4 + j] = lo | (hi << 16);
}

// ---------------- fused pre-BiLSTM scan (f32x2 full-precision packed FMA) ----------------
// grid = 256: bx<128 -> passage (b=bx&63, d=bx>>6, T=600); bx>=128 -> question (T=60).
__global__ __launch_bounds__(384, 1) void pre_scan_fused(
    const float* __restrict__ Xp, const float* __restrict__ Xq,
    const float* __restrict__ mask_p, const float* __restrict__ mask_q,
    const float* __restrict__ Whh,
    float* __restrict__ Hp, float* __restrict__ Hq)
{
    __shared__ __align__(16) float h_s[128];
    __shared__ __align__(16) float c_s[128];
    __shared__ float gates[384];
    int bx = blockIdx.x;
    const float* X; const float* mask; float* Hout; int T, b, d;
    if (bx < 128) { X = Xp; mask = mask_p; Hout = Hp; T = TPLEN; b = bx & 63; d = bx >> 6; }
    else { int v = bx - 128; X = Xq; mask = mask_q; Hout = Hq; T = TQLEN; b = v & 63; d = v >> 6; }
    int j = threadIdx.x;

    // weight row as 32 ulonglong2 (fp32 pairs; full precision)
    ulonglong2 w2[32];
    const ulonglong2* wrow = (const ulonglong2*)(Whh + j * 128);
#pragma unroll
    for (int i = 0; i < 32; i++) w2[i] = wrow[i];

    if (j < 128) { h_s[j] = 0.f; c_s[j] = 0.f; }
    __syncthreads();

    float xin = X[((long long)(d ? (T - 1) : 0) * BATCH + b) * 384 + j];

    for (int t = 0; t < T; t++) {
        int td = d ? (T - 1 - t) : t;
        float xcur = xin;
        if (t + 1 < T) {
            int tdn = d ? (T - 2 - t) : (t + 1);
            xin = X[((long long)tdn * BATCH + b) * 384 + j];
        }
        const ulonglong2* hp = (const ulonglong2*)h_s;
        ull a0 = pack2(0.f, 0.f), a1 = pack2(0.f, 0.f);
#pragma unroll 8
        for (int i = 0; i < 32; i++) {
            ulonglong2 hv = hp[i];
            a0 = fma2(w2[i].x, hv.x, a0);
            a1 = fma2(w2[i].y, hv.y, a1);
        }
        float2 f0 = unpack2(a0), f1 = unpack2(a1);
        gates[j] = xcur + ((f0.x + f0.y) + (f1.x + f1.y));
        __syncthreads();
        if (j < 128) {
            float ig = gates[j], fg = gates[128 + j], gg = gates[256 + j];
            float m = mask[td * BATCH + b];
            float c2 = (sigf(fg) * c_s[j] + sigf(ig) * tanhf(gg)) * m;
            float h2 = tanhf(c2);
            c_s[j] = c2;
            h_s[j] = h2;
            Hout[((long long)td * BATCH + b) * 256 + d * 128 + j] = h2;
        }
        __syncthreads();
    }
}

// ---------------- Match-LSTM scan (v7: smem weight cache + Yq in registers) ----------------
// grid = 128 (b = bx&63, d = bx>>6), block = 512.
#define NCKC 26                         // cached k-chunks (of 32)
#define MS_AQ    0                       // 60*256
#define MS_WA    (MS_AQ + 60 * 256)      // 256
#define MS_U     (MS_WA + 256)           // 256
#define MS_G     (MS_U + 256)            // 512 (floats; aliased as 256 ull partials)
#define MS_HS    (MS_G + 512)            // 256  (128 ull h-splats)
#define MS_AL    (MS_HS + 256)           // 64   (scalar logits)
#define MS_AL2   (MS_AL + 64)            // 128  (64 ull splatted alphas)
#define MS_WC    (MS_AL2 + 128)          // NCKC*384*4 u32 weight cache
#define MS_TOTAL (MS_WC + NCKC * 384 * 4)
#define MATCH_SMEM_BYTES (MS_TOTAL * 4)

__global__ __launch_bounds__(512, 1) void match_scan(
    const float* __restrict__ ap,       // [600,64,256]
    const float* __restrict__ xp,       // [600,64,512]
    const float* __restrict__ aq,       // [60,64,256]
    const float* __restrict__ Yq,       // [60,64,512]
    const unsigned* __restrict__ WcatB, // k-blocked bf16 pairs
    const float* __restrict__ Wa,       // [256]
    const float* __restrict__ ba,       // [1]
    const float* __restrict__ mask,     // [600,64]
    float* __restrict__ out)            // [600,64,256]
{
    extern __shared__ __align__(16) float sm[];
    float* aq_s = sm + MS_AQ;
    float* Wa_s = sm + MS_WA;
    float* u_s  = sm + MS_U;
    float* g_s  = sm + MS_G;
    ull*   g2u  = (ull*)g_s;
    ull*   hsp  = (ull*)(sm + MS_HS);
    float* al_s = sm + MS_AL;
    ull*   al2  = (ull*)(sm + MS_AL2);
    unsigned* Wc = (unsigned*)(sm + MS_WC);

    int b = blockIdx.x & 63;
    int d = blockIdx.x >> 6;
    int tid = threadIdx.x;
    int lane = tid & 31;
    int gp = tid >> 1, half = tid & 1;

    // ---- stage weight cache (26 k-chunks, 160KB)
    for (int idx = tid; idx < NCKC * 384; idx += 512)
        ((uint4*)Wc)[idx] = ((const uint4*)WcatB)[idx];

    // ---- stage aq
    for (int idx = tid; idx < 60 * 64; idx += 512) {
        int tq = idx >> 6, jj = idx & 63;
        ((float4*)aq_s)[idx] = *(const float4*)(aq + ((long long)tq * BATCH + b) * 256 + jj * 4);
    }
    if (tid < 256) Wa_s[tid] = Wa[tid];
    if (tid < 128) hsp[tid] = 0ull;
    float bav = ba[0];
    float c_reg = 0.f;   // cell state for tid<128 (unit k = tid)

    // ---- Yq into registers: thread (gp, half) holds tq = half*30 .. half*30+29
    ull yqr[30];
#pragma unroll
    for (int i = 0; i < 30; i++)
        yqr[i] = *((const ull*)(Yq + ((long long)(half * 30 + i) * BATCH + b) * 512) + gp);

    __syncthreads();

    // prefetch step-0 init (ap for u-cols, xp for gate-cols)
    float2 initv = make_float2(0.f, 0.f);
    {
        int td0 = d ? (TPLEN - 1) : 0;
        if (tid < 128)
            initv = *(const float2*)(ap + ((long long)td0 * BATCH + b) * 256 + 2 * tid);
        else if (tid < 384)
            initv = *(const float2*)(xp + ((long long)td0 * BATCH + b) * 512 + 2 * (tid - 128));
    }

    for (int t = 0; t < TPLEN; t++) {
        int td = d ? (TPLEN - 1 - t) : t;

        // ---- Phase A: [u | gates](768 cols) = init + h @ Wcat
        if (tid < 384) {
            int cp = tid;
            const uint4* wg = (const uint4*)WcatB + cp;
            uint4 w26 = wg[26 * 384];
            uint4 w27 = wg[27 * 384];
            uint4 w28 = wg[28 * 384];
            uint4 w29 = wg[29 * 384];
            uint4 w30 = wg[30 * 384];
            uint4 w31 = wg[31 * 384];
            ull a0 = pack2(initv.x, initv.y);
            ull a1 = pack2(0.f, 0.f);
            if (t + 1 < TPLEN) {
                int tdn = d ? (TPLEN - 2 - t) : (t + 1);
                if (cp < 128)
                    initv = *(const float2*)(ap + ((long long)tdn * BATCH + b) * 256 + 2 * cp);
                else
                    initv = *(const float2*)(xp + ((long long)tdn * BATCH + b) * 512 + 2 * (cp - 128));
            }
            const ulonglong2* hp2 = (const ulonglong2*)hsp;
#pragma unroll 13
            for (int kc = 0; kc < NCKC; kc++) {
                uint4 w4 = ((const uint4*)Wc)[kc * 384 + cp];
                ulonglong2 ha = hp2[2 * kc];
                ulonglong2 hb = hp2[2 * kc + 1];
                a0 = fma2(bf2(w4.x), ha.x, a0);
                a1 = fma2(bf2(w4.y), ha.y, a1);
                a0 = fma2(bf2(w4.z), hb.x, a0);
                a1 = fma2(bf2(w4.w), hb.y, a1);
            }
            {
                ulonglong2 ha, hb;
                uint4 w4;
#define RES_CHUNK(KC, W4) \
                w4 = W4; \
                ha = hp2[2 * (KC)]; hb = hp2[2 * (KC) + 1]; \
                a0 = fma2(bf2(w4.x), ha.x, a0); \
                a1 = fma2(bf2(w4.y), ha.y, a1); \
                a0 = fma2(bf2(w4.z), hb.x, a0); \
                a1 = fma2(bf2(w4.w), hb.y, a1);
                RES_CHUNK(26, w26) RES_CHUNK(27, w27) RES_CHUNK(28, w28)
                RES_CHUNK(29, w29) RES_CHUNK(30, w30) RES_CHUNK(31, w31)
#undef RES_CHUNK
            }
            float2 f0 = unpack2(a0), f1 = unpack2(a1);
            f0.x += f1.x; f0.y += f1.y;
            if (cp < 128) *(float2*)&u_s[2 * cp] = f0;
            else          g2u[cp - 128] = pack2(f0.x, f0.y);
        }
        __syncthreads();

        // ---- Phase 2: logits e[tq] = ba + sum_i Wa[i]*tanh(aq[tq,i] + u[i])
        {
            int tq = tid >> 3, l8 = tid & 7;
            if (tq < TQLEN) {
                const float* aqr = aq_s + tq * 256;
                float a0 = 0.f;
#pragma unroll
                for (int ii = 0; ii < 32; ii++) {
                    int i = l8 * 32 + ((ii + lane) & 31);  // bank-stagger
                    a0 += Wa_s[i] * tanh_ap(aqr[i] + u_s[i]);
                }
                a0 += __shfl_xor_sync(0xffffffffu, a0, 1);
                a0 += __shfl_xor_sync(0xffffffffu, a0, 2);
                a0 += __shfl_xor_sync(0xffffffffu, a0, 4);
                if (l8 == 0) al_s[tq] = a0 + bav;
            }
        }
        __syncthreads();

        // ---- Phase 3: softmax over TQ (warp 0), write splatted alphas
        if (tid < 32) {
            float e0 = (lane < TQLEN) ? al_s[lane] : -1e30f;
            float e1 = (lane + 32 < TQLEN) ? al_s[lane + 32] : -1e30f;
            float mx = fmaxf(e0, e1);
#pragma unroll
            for (int o = 16; o; o >>= 1) mx = fmaxf(mx, __shfl_xor_sync(0xffffffffu, mx, o));
            float s0 = (lane < TQLEN) ? __expf(e0 - mx) : 0.f;
            float s1 = (lane + 32 < TQLEN) ? __expf(e1 - mx) : 0.f;
            float s = s0 + s1;
#pragma unroll
            for (int o = 16; o; o >>= 1) s += __shfl_xor_sync(0xffffffffu, s, o);
            float inv = 1.0f / s;
            if (lane < TQLEN) { float v = s0 * inv; al2[lane] = pack2(v, v); }
            if (lane + 32 < TQLEN) { float v = s1 * inv; al2[lane + 32] = pack2(v, v); }
        }
        __syncthreads();

        // ---- Phase 4: gates += sum_tq alpha[tq] * Yq[tq]; Yq from registers
        {
            ull a = (half == 0) ? g2u[gp] : pack2(0.f, 0.f);
#pragma unroll
            for (int i = 0; i < 30; i++)
                a = fma2(al2[half * 30 + i], yqr[i], a);
            ull other = __shfl_xor_sync(0xffffffffu, a, 1);
            if (half == 0) {
                float2 fa = unpack2(a), fo = unpack2(other);
                fa.x += fo.x; fa.y += fo.y;
                *(float2*)&g_s[2 * gp] = fa;
            }
        }
        __syncthreads();

        // ---- Phase 5: LSTM cell (c in registers), write h splats + output
        if (tid < 128) {
            int k = tid;
            float ig = g_s[k], fg = g_s[128 + k], gg = g_s[256 + k], og = g_s[384 + k];
            float m = mask[td * BATCH + b];
            float c2 = sigf(fg) * c_reg + sigf(ig) * tanhf(gg);
            float h2 = sigf(og) * tanhf(c2);
            c2 *= m; h2 *= m;
            c_reg = c2;
            hsp[k] = pack2(h2, h2);
            out[((long long)td * BATCH + b) * 256 + d * 128 + k] = h2;
        }
        __syncthreads();
    }
}

// ---------------- host ----------------
static void launch_gemm(const float* A, const float* W, const float* bias, float* C,
                        int M, int N, int K, int ldw, int wcol0)
{
    dim3 g(N / 128, M / 128);
    gemm_bias<<<g, 256>>>(A, W, bias, C, M, N, K, ldw, wcol0, bias != nullptr ? 1 : 0);
}

extern "C" void kernel_launch(void* const* d_in, const int* in_sizes, int n_in,
                              void* d_out, int out_size)
{
    const float* passage  = (const float*)d_in[0];
    const float* question = (const float*)d_in[1];
    const float* mask_p   = (const float*)d_in[2];
    const float* mask_q   = (const float*)d_in[3];
    const float* pre0_Wih = (const float*)d_in[4];
    const float* pre0_Whh = (const float*)d_in[5];
    const float* pre0_b   = (const float*)d_in[6];
    const float* pre1_Wih = (const float*)d_in[7];
    const float* pre1_Whh = (const float*)d_in[8];
    const float* pre1_b   = (const float*)d_in[9];
    const float* mq_Wq    = (const float*)d_in[10];
    const float* mq_Wp    = (const float*)d_in[11];
    const float* mq_bp    = (const float*)d_in[12];
    const float* mq_Wh    = (const float*)d_in[13];
    const float* mq_Wa    = (const float*)d_in[14];
    const float* mq_ba    = (const float*)d_in[15];
    const float* mq_Wih   = (const float*)d_in[16];
    const float* mq_Whh   = (const float*)d_in[17];
    const float* mq_b     = (const float*)d_in[18];
    float* out = (float*)d_out;

    float* s = nullptr;
    cudaGetSymbolAddress((void**)&s, g_scratch);

    float* X0p = s + O_X0p;
    float* X0q = s + O_X0q;
    float* Hp0 = s + O_Hp0;
    float* Hq0 = s + O_Hq0;
    float* Hp1 = s + O_Hp1;
    float* Hq1 = s + O_Hq1;
    float* aqb = s + O_aq;
    float* apb = s + O_ap;
    float* xpb = s + O_xp;
    float* Yqb = s + O_Yq;
    unsigned* WcatB = (unsigned*)(s + O_WCB);

    cudaFuncSetAttribute(match_scan, cudaFuncAttributeMaxDynamicSharedMemorySize,
                         MATCH_SMEM_BYTES);

    // bf16 weight pack for the match scan (independent of data path)
    make_wcatb<<<(128 * 384 + 255) / 256, 256>>>(mq_Wh, mq_Whh, WcatB);

    // ---- pre layer 0 (i,f,g gates only: 384 rows) ----
    launch_gemm(passage,  pre0_Wih, pre0_b, X0p, TPLEN * BATCH, 384, 344, 344, 0);
    launch_gemm(question, pre0_Wih, pre0_b, X0q, TQLEN * BATCH, 384, 344, 344, 0);
    pre_scan_fused<<<256, 384>>>(X0p, X0q, mask_p, mask_q, pre0_Whh, Hp0, Hq0);

    // ---- pre layer 1: Hp0/Hq0 and X0p/X0q contiguous -> one concatenated GEMM ----
    launch_gemm(Hp0, pre1_Wih, pre1_b, X0p, (TPLEN + TQLEN) * BATCH, 384, 256, 256, 0);
    pre_scan_fused<<<256, 384>>>(X0p, X0q, mask_p, mask_q, pre1_Whh, Hp1, Hq1);

    // ---- match precompute ----
    launch_gemm(Hq1, mq_Wq, nullptr, aqb, TQLEN * BATCH, 256, 256, 256, 0);
    launch_gemm(Hp1, mq_Wp, mq_bp,   apb, TPLEN * BATCH, 256, 256, 256, 0);
    launch_gemm(Hp1, mq_Wih, mq_b,   xpb, TPLEN * BATCH, 512, 256, 512, 0);
    launch_gemm(Hq1, mq_Wih, nullptr, Yqb, TQLEN * BATCH, 512, 256, 512, 256);

    // ---- match scan ----
    match_scan<<<2 * BATCH, 512, MATCH_SMEM_BYTES>>>(
        apb, xpb, aqb, Yqb, WcatB, mq_Wa, mq_ba, mask_p, out);

    (void)in_sizes; (void)n_in; (void)out_size;
}

// round 16
// speedup vs baseline: 1.3405x; 1.0027x over previous
#include <cuda_runtime.h>
#include <cuda_bf16.h>
#include <math.h>
#include <stdint.h>

// ---------------- problem constants ----------------
#define TPLEN 600
#define TQLEN 60
#define BATCH 64
// H=256, H2=128, EMB=344

// ---------------- scratch ----------------
#define N_XP   (600LL*64*384)
#define N_XQ   (60LL*64*384)
#define N_HP   (600LL*64*256)
#define N_HQ   (60LL*64*256)
#define N_XPM  (600LL*64*512)
#define N_YQ   (60LL*64*512)
#define N_WCATB (128LL*384)          // u32 elements (bf16 pairs), k-blocked layout

#define O_X0p  0LL
#define O_X0q  (O_X0p + N_XP)
#define O_Hp0  (O_X0q + N_XQ)
#define O_Hq0  (O_Hp0 + N_HP)
#define O_Hp1  (O_Hq0 + N_HQ)
#define O_Hq1  (O_Hp1 + N_HP)
#define O_aq   (O_Hq1 + N_HQ)
#define O_ap   (O_aq  + N_HQ)
#define O_xp   (O_ap  + N_HP)
#define O_Yq   (O_xp  + N_XPM)
#define O_WCB  (O_Yq  + N_YQ)
#define SCRATCH_TOTAL (O_WCB + N_WCATB)

__device__ __align__(16) float g_scratch[SCRATCH_TOTAL];

// ---------------- helpers ----------------
__device__ __forceinline__ float sigf(float x) { return 1.0f / (1.0f + __expf(-x)); }
__device__ __forceinline__ float tanh_ap(float x) {
    float y;
    asm("tanh.approx.f32 %0, %1;" : "=f"(y) : "f"(x));
    return y;
}
typedef unsigned long long ull;
__device__ __forceinline__ ull pack2(float x, float y) {
    ull r; asm("mov.b64 %0, {%1, %2};" : "=l"(r) : "f"(x), "f"(y)); return r;
}
__device__ __forceinline__ float2 unpack2(ull v) {
    float2 f; asm("mov.b64 {%0, %1}, %2;" : "=f"(f.x), "=f"(f.y) : "l"(v)); return f;
}
__device__ __forceinline__ ull fma2(ull a, ull b, ull c) {
    ull d; asm("fma.rn.f32x2 %0, %1, %2, %3;" : "=l"(d) : "l"(a), "l"(b), "l"(c)); return d;
}
// expand packed bf16 pair (lo,hi halves of u32) to f32x2
__device__ __forceinline__ ull bf2(unsigned v) {
    return pack2(__uint_as_float(v << 16), __uint_as_float(v & 0xFFFF0000u));
}

// ---------------- fused GEMM ----------------
// C[M,N] = A[M,K] @ W[N, wcol0:wcol0+K]^T (+ bias). Up to 4 configs per launch.
// Dispatch is SEQUENTIAL (ci==t guard) — fixes the R8 misroute bug where later
// configs were tested after a match and blocks got routed OOB.
// Optional tail blocks (bx >= nbTotal) pack WcatB.
struct GemmCfg {
    const float* A; const float* W; const float* bias; float* C;
    int M, N, K, ldw, wcol0, hasBias, nbx, nby;
};
struct GemmCfg4 { GemmCfg c[4]; };

__global__ __launch_bounds__(256, 2) void gemm_fused(
    GemmCfg4 cfgs, int ncfg, int nbTotal,
    const float* __restrict__ Wh, const float* __restrict__ Whh,
    unsigned* __restrict__ WcatB)
{
    int bx = blockIdx.x;
    int tid = threadIdx.x;

    if (bx >= nbTotal) {
        // ---- WcatB pack tail (64 blocks), k-blocked layout ----
        int pb = bx - nbTotal;
        for (int i = pb * 256 + tid; i < 128 * 384; i += 64 * 256) {
            int k = i / 384, cc = i % 384;
            int c0i = 2 * cc, c1i = 2 * cc + 1;
            float w0 = (c0i < 256) ? Wh[c0i * 128 + k] : Whh[(c0i - 256) * 128 + k];
            float w1 = (c1i < 256) ? Wh[c1i * 128 + k] : Whh[(c1i - 256) * 128 + k];
            unsigned lo = (unsigned)__bfloat16_as_ushort(__float2bfloat16(w0));
            unsigned hi = (unsigned)__bfloat16_as_ushort(__float2bfloat16(w1));
            int kc = k >> 2, j = k & 3;
            WcatB[(kc * 384 + cc) * 4 + j] = lo | (hi << 16);
        }
        return;
    }

    // ---- sequential config dispatch (fixed) ----
    int rem = bx, ci = 0;
#pragma unroll
    for (int t = 0; t < 4; t++) {
        if (t < ncfg) {
            int nb = cfgs.c[t].nbx * cfgs.c[t].nby;
            if (ci == t && rem >= nb) { rem -= nb; ci = t + 1; }
        }
    }
    GemmCfg c = cfgs.c[ci];
    int bn = rem % c.nbx, bm = rem / c.nbx;

    __shared__ float As[2][8][132];
    __shared__ float Ws[2][8][132];
    int tm = tid >> 4, tn = tid & 15;
    int lrow = tid >> 1;
    int kq   = (tid & 1) * 4;

    const float* Ag = c.A + (long long)(bm * 128 + lrow) * c.K + kq;
    const float* Wg = c.W + (long long)(bn * 128 + lrow) * c.ldw + c.wcol0 + kq;

    // packed accumulators: acc2[i][j] = (C[i][2j], C[i][2j+1])
    ull acc2[8][4];
#pragma unroll
    for (int i = 0; i < 8; i++)
#pragma unroll
        for (int j = 0; j < 4; j++) acc2[i][j] = pack2(0.f, 0.f);

    float4 av = *(const float4*)Ag;
    float4 wv = *(const float4*)Wg;
    As[0][kq + 0][lrow] = av.x; As[0][kq + 1][lrow] = av.y;
    As[0][kq + 2][lrow] = av.z; As[0][kq + 3][lrow] = av.w;
    Ws[0][kq + 0][lrow] = wv.x; Ws[0][kq + 1][lrow] = wv.y;
    Ws[0][kq + 2][lrow] = wv.z; Ws[0][kq + 3][lrow] = wv.w;

    int nOct = c.K >> 3;
    for (int it = 0; it < nOct; it++) {
        __syncthreads();
        int cur = it & 1;
        if (it + 1 < nOct) {
            av = *(const float4*)(Ag + (it + 1) * 8);
            wv = *(const float4*)(Wg + (it + 1) * 8);
        }
#pragma unroll
        for (int kk = 0; kk < 8; kk++) {
            float4 a0 = *(const float4*)&As[cur][kk][tm * 8];
            float4 a1 = *(const float4*)&As[cur][kk][tm * 8 + 4];
            const ull* bp = (const ull*)&Ws[cur][kk][tn * 8];
            ull b0 = bp[0], b1 = bp[1], b2 = bp[2], b3 = bp[3];
            float ar[8] = {a0.x, a0.y, a0.z, a0.w, a1.x, a1.y, a1.z, a1.w};
#pragma unroll
            for (int i = 0; i < 8; i++) {
                ull as = pack2(ar[i], ar[i]);
                acc2[i][0] = fma2(as, b0, acc2[i][0]);
                acc2[i][1] = fma2(as, b1, acc2[i][1]);
                acc2[i][2] = fma2(as, b2, acc2[i][2]);
                acc2[i][3] = fma2(as, b3, acc2[i][3]);
            }
        }
        if (it + 1 < nOct) {
            int nxt = cur ^ 1;
            As[nxt][kq + 0][lrow] = av.x; As[nxt][kq + 1][lrow] = av.y;
            As[nxt][kq + 2][lrow] = av.z; As[nxt][kq + 3][lrow] = av.w;
            Ws[nxt][kq + 0][lrow] = wv.x; Ws[nxt][kq + 1][lrow] = wv.y;
            Ws[nxt][kq + 2][lrow] = wv.z; Ws[nxt][kq + 3][lrow] = wv.w;
        }
    }

    float bv[8];
#pragma unroll
    for (int j = 0; j < 8; j++)
        bv[j] = c.hasBias ? c.bias[bn * 128 + tn * 8 + j] : 0.0f;

#pragma unroll
    for (int i = 0; i < 8; i++) {
        long long crow = (long long)(bm * 128 + tm * 8 + i) * c.N + bn * 128 + tn * 8;
        float2 c0 = unpack2(acc2[i][0]);
        float2 c1 = unpack2(acc2[i][1]);
        float2 c2 = unpack2(acc2[i][2]);
        float2 c3 = unpack2(acc2[i][3]);
        float4 s0 = make_float4(c0.x + bv[0], c0.y + bv[1], c1.x + bv[2], c1.y + bv[3]);
        float4 s1 = make_float4(c2.x + bv[4], c2.y + bv[5], c3.x + bv[6], c3.y + bv[7]);
        *(float4*)(c.C + crow) = s0;
        *(float4*)(c.C + crow + 4) = s1;
    }
}

// ---------------- fused pre-BiLSTM scan (f32x2 full-precision packed FMA) ----------------
// grid = 256: bx<128 -> passage (b=bx&63, d=bx>>6, T=600); bx>=128 -> question (T=60).
__global__ __launch_bounds__(384, 1) void pre_scan_fused(
    const float* __restrict__ Xp, const float* __restrict__ Xq,
    const float* __restrict__ mask_p, const float* __restrict__ mask_q,
    const float* __restrict__ Whh,
    float* __restrict__ Hp, float* __restrict__ Hq)
{
    __shared__ __align__(16) float h_s[128];
    __shared__ __align__(16) float c_s[128];
    __shared__ float gates[384];
    int bx = blockIdx.x;
    const float* X; const float* mask; float* Hout; int T, b, d;
    if (bx < 128) { X = Xp; mask = mask_p; Hout = Hp; T = TPLEN; b = bx & 63; d = bx >> 6; }
    else { int v = bx - 128; X = Xq; mask = mask_q; Hout = Hq; T = TQLEN; b = v & 63; d = v >> 6; }
    int j = threadIdx.x;

    ulonglong2 w2[32];
    const ulonglong2* wrow = (const ulonglong2*)(Whh + j * 128);
#pragma unroll
    for (int i = 0; i < 32; i++) w2[i] = wrow[i];

    if (j < 128) { h_s[j] = 0.f; c_s[j] = 0.f; }
    __syncthreads();

    float xin = X[((long long)(d ? (T - 1) : 0) * BATCH + b) * 384 + j];

    for (int t = 0; t < T; t++) {
        int td = d ? (T - 1 - t) : t;
        float xcur = xin;
        if (t + 1 < T) {
            int tdn = d ? (T - 2 - t) : (t + 1);
            xin = X[((long long)tdn * BATCH + b) * 384 + j];
        }
        const ulonglong2* hp = (const ulonglong2*)h_s;
        ull a0 = pack2(0.f, 0.f), a1 = pack2(0.f, 0.f);
#pragma unroll 8
        for (int i = 0; i < 32; i++) {
            ulonglong2 hv = hp[i];
            a0 = fma2(w2[i].x, hv.x, a0);
            a1 = fma2(w2[i].y, hv.y, a1);
        }
        float2 f0 = unpack2(a0), f1 = unpack2(a1);
        gates[j] = xcur + ((f0.x + f0.y) + (f1.x + f1.y));
        __syncthreads();
        if (j < 128) {
            float ig = gates[j], fg = gates[128 + j], gg = gates[256 + j];
            float m = mask[td * BATCH + b];
            float c2 = (sigf(fg) * c_s[j] + sigf(ig) * tanhf(gg)) * m;
            float h2 = tanhf(c2);
            c_s[j] = c2;
            h_s[j] = h2;
            Hout[((long long)td * BATCH + b) * 256 + d * 128 + j] = h2;
        }
        __syncthreads();
    }
}

// ---------------- Match-LSTM scan (v7: smem weight cache + Yq in registers) ----------------
// grid = 128 (b = bx&63, d = bx>>6), block = 512.
#define NCKC 26                         // cached k-chunks (of 32)
#define MS_AQ    0                       // 60*256
#define MS_WA    (MS_AQ + 60 * 256)      // 256
#define MS_U     (MS_WA + 256)           // 256
#define MS_G     (MS_U + 256)            // 512 (floats; aliased as 256 ull partials)
#define MS_HS    (MS_G + 512)            // 256  (128 ull h-splats)
#define MS_AL    (MS_HS + 256)           // 64   (scalar logits)
#define MS_AL2   (MS_AL + 64)            // 128  (64 ull splatted alphas)
#define MS_WC    (MS_AL2 + 128)          // NCKC*384*4 u32 weight cache
#define MS_TOTAL (MS_WC + NCKC * 384 * 4)
#define MATCH_SMEM_BYTES (MS_TOTAL * 4)

__global__ __launch_bounds__(512, 1) void match_scan(
    const float* __restrict__ ap,       // [600,64,256]
    const float* __restrict__ xp,       // [600,64,512]
    const float* __restrict__ aq,       // [60,64,256]
    const float* __restrict__ Yq,       // [60,64,512]
    const unsigned* __restrict__ WcatB, // k-blocked bf16 pairs
    const float* __restrict__ Wa,       // [256]
    const float* __restrict__ ba,       // [1]
    const float* __restrict__ mask,     // [600,64]
    float* __restrict__ out)            // [600,64,256]
{
    extern __shared__ __align__(16) float sm[];
    float* aq_s = sm + MS_AQ;
    float* Wa_s = sm + MS_WA;
    float* u_s  = sm + MS_U;
    float* g_s  = sm + MS_G;
    ull*   g2u  = (ull*)g_s;
    ull*   hsp  = (ull*)(sm + MS_HS);
    float* al_s = sm + MS_AL;
    ull*   al2  = (ull*)(sm + MS_AL2);
    unsigned* Wc = (unsigned*)(sm + MS_WC);

    int b = blockIdx.x & 63;
    int d = blockIdx.x >> 6;
    int tid = threadIdx.x;
    int lane = tid & 31;
    int gp = tid >> 1, half = tid & 1;

    // ---- stage weight cache (26 k-chunks, 160KB)
    for (int idx = tid; idx < NCKC * 384; idx += 512)
        ((uint4*)Wc)[idx] = ((const uint4*)WcatB)[idx];

    // ---- stage aq
    for (int idx = tid; idx < 60 * 64; idx += 512) {
        int tq = idx >> 6, jj = idx & 63;
        ((float4*)aq_s)[idx] = *(const float4*)(aq + ((long long)tq * BATCH + b) * 256 + jj * 4);
    }
    if (tid < 256) Wa_s[tid] = Wa[tid];
    if (tid < 128) hsp[tid] = 0ull;
    float bav = ba[0];
    float c_reg = 0.f;   // cell state for tid<128 (unit k = tid)

    // ---- Yq into registers: thread (gp, half) holds tq = half*30 .. half*30+29
    ull yqr[30];
#pragma unroll
    for (int i = 0; i < 30; i++)
        yqr[i] = *((const ull*)(Yq + ((long long)(half * 30 + i) * BATCH + b) * 512) + gp);

    __syncthreads();

    // prefetch step-0 init (ap for u-cols, xp for gate-cols)
    float2 initv = make_float2(0.f, 0.f);
    {
        int td0 = d ? (TPLEN - 1) : 0;
        if (tid < 128)
            initv = *(const float2*)(ap + ((long long)td0 * BATCH + b) * 256 + 2 * tid);
        else if (tid < 384)
            initv = *(const float2*)(xp + ((long long)td0 * BATCH + b) * 512 + 2 * (tid - 128));
    }

    for (int t = 0; t < TPLEN; t++) {
        int td = d ? (TPLEN - 1 - t) : t;

        // ---- Phase A: [u | gates](768 cols) = init + h @ Wcat
        if (tid < 384) {
            int cp = tid;
            const uint4* wg = (const uint4*)WcatB + cp;
            uint4 w26 = wg[26 * 384];
            uint4 w27 = wg[27 * 384];
            uint4 w28 = wg[28 * 384];
            uint4 w29 = wg[29 * 384];
            uint4 w30 = wg[30 * 384];
            uint4 w31 = wg[31 * 384];
            ull a0 = pack2(initv.x, initv.y);
            ull a1 = pack2(0.f, 0.f);
            if (t + 1 < TPLEN) {
                int tdn = d ? (TPLEN - 2 - t) : (t + 1);
                if (cp < 128)
                    initv = *(const float2*)(ap + ((long long)tdn * BATCH + b) * 256 + 2 * cp);
                else
                    initv = *(const float2*)(xp + ((long long)tdn * BATCH + b) * 512 + 2 * (cp - 128));
            }
            const ulonglong2* hp2 = (const ulonglong2*)hsp;
#pragma unroll 13
            for (int kc = 0; kc < NCKC; kc++) {
                uint4 w4 = ((const uint4*)Wc)[kc * 384 + cp];
                ulonglong2 ha = hp2[2 * kc];
                ulonglong2 hb = hp2[2 * kc + 1];
                a0 = fma2(bf2(w4.x), ha.x, a0);
                a1 = fma2(bf2(w4.y), ha.y, a1);
                a0 = fma2(bf2(w4.z), hb.x, a0);
                a1 = fma2(bf2(w4.w), hb.y, a1);
            }
            {
                ulonglong2 ha, hb;
                uint4 w4;
#define RES_CHUNK(KC, W4) \
                w4 = W4; \
                ha = hp2[2 * (KC)]; hb = hp2[2 * (KC) + 1]; \
                a0 = fma2(bf2(w4.x), ha.x, a0); \
                a1 = fma2(bf2(w4.y), ha.y, a1); \
                a0 = fma2(bf2(w4.z), hb.x, a0); \
                a1 = fma2(bf2(w4.w), hb.y, a1);
                RES_CHUNK(26, w26) RES_CHUNK(27, w27) RES_CHUNK(28, w28)
                RES_CHUNK(29, w29) RES_CHUNK(30, w30) RES_CHUNK(31, w31)
#undef RES_CHUNK
            }
            float2 f0 = unpack2(a0), f1 = unpack2(a1);
            f0.x += f1.x; f0.y += f1.y;
            if (cp < 128) *(float2*)&u_s[2 * cp] = f0;
            else          g2u[cp - 128] = pack2(f0.x, f0.y);
        }
        __syncthreads();

        // ---- Phase 2: logits e[tq] = ba + sum_i Wa[i]*tanh(aq[tq,i] + u[i])
        {
            int tq = tid >> 3, l8 = tid & 7;
            if (tq < TQLEN) {
                const float* aqr = aq_s + tq * 256;
                float a0 = 0.f;
#pragma unroll
                for (int ii = 0; ii < 32; ii++) {
                    int i = l8 * 32 + ((ii + lane) & 31);  // bank-stagger
                    a0 += Wa_s[i] * tanh_ap(aqr[i] + u_s[i]);
                }
                a0 += __shfl_xor_sync(0xffffffffu, a0, 1);
                a0 += __shfl_xor_sync(0xffffffffu, a0, 2);
                a0 += __shfl_xor_sync(0xffffffffu, a0, 4);
                if (l8 == 0) al_s[tq] = a0 + bav;
            }
        }
        __syncthreads();

        // ---- Phase 3: softmax over TQ (warp 0), write splatted alphas
        if (tid < 32) {
            float e0 = (lane < TQLEN) ? al_s[lane] : -1e30f;
            float e1 = (lane + 32 < TQLEN) ? al_s[lane + 32] : -1e30f;
            float mx = fmaxf(e0, e1);
#pragma unroll
            for (int o = 16; o; o >>= 1) mx = fmaxf(mx, __shfl_xor_sync(0xffffffffu, mx, o));
            float s0 = (lane < TQLEN) ? __expf(e0 - mx) : 0.f;
            float s1 = (lane + 32 < TQLEN) ? __expf(e1 - mx) : 0.f;
            float s = s0 + s1;
#pragma unroll
            for (int o = 16; o; o >>= 1) s += __shfl_xor_sync(0xffffffffu, s, o);
            float inv = 1.0f / s;
            if (lane < TQLEN) { float v = s0 * inv; al2[lane] = pack2(v, v); }
            if (lane + 32 < TQLEN) { float v = s1 * inv; al2[lane + 32] = pack2(v, v); }
        }
        __syncthreads();

        // ---- Phase 4: gates += sum_tq alpha[tq] * Yq[tq]; Yq from registers
        {
            ull a = (half == 0) ? g2u[gp] : pack2(0.f, 0.f);
#pragma unroll
            for (int i = 0; i < 30; i++)
                a = fma2(al2[half * 30 + i], yqr[i], a);
            ull other = __shfl_xor_sync(0xffffffffu, a, 1);
            if (half == 0) {
                float2 fa = unpack2(a), fo = unpack2(other);
                fa.x += fo.x; fa.y += fo.y;
                *(float2*)&g_s[2 * gp] = fa;
            }
        }
        __syncthreads();

        // ---- Phase 5: LSTM cell (c in registers), write h splats + output
        if (tid < 128) {
            int k = tid;
            float ig = g_s[k], fg = g_s[128 + k], gg = g_s[256 + k], og = g_s[384 + k];
            float m = mask[td * BATCH + b];
            float c2 = sigf(fg) * c_reg + sigf(ig) * tanhf(gg);
            float h2 = sigf(og) * tanhf(c2);
            c2 *= m; h2 *= m;
            c_reg = c2;
            hsp[k] = pack2(h2, h2);
            out[((long long)td * BATCH + b) * 256 + d * 128 + k] = h2;
        }
        __syncthreads();
    }
}

// ---------------- host ----------------
static GemmCfg mk(const float* A, const float* W, const float* bias, float* C,
                  int M, int N, int K, int ldw, int wcol0)
{
    GemmCfg c;
    c.A = A; c.W = W; c.bias = bias; c.C = C;
    c.M = M; c.N = N; c.K = K; c.ldw = ldw; c.wcol0 = wcol0;
    c.hasBias = (bias != nullptr) ? 1 : 0;
    c.nbx = N / 128; c.nby = M / 128;
    return c;
}

extern "C" void kernel_launch(void* const* d_in, const int* in_sizes, int n_in,
                              void* d_out, int out_size)
{
    const float* passage  = (const float*)d_in[0];
    const float* question = (const float*)d_in[1];
    const float* mask_p   = (const float*)d_in[2];
    const float* mask_q   = (const float*)d_in[3];
    const float* pre0_Wih = (const float*)d_in[4];
    const float* pre0_Whh = (const float*)d_in[5];
    const float* pre0_b   = (const float*)d_in[6];
    const float* pre1_Wih = (const float*)d_in[7];
    const float* pre1_Whh = (const float*)d_in[8];
    const float* pre1_b   = (const float*)d_in[9];
    const float* mq_Wq    = (const float*)d_in[10];
    const float* mq_Wp    = (const float*)d_in[11];
    const float* mq_bp    = (const float*)d_in[12];
    const float* mq_Wh    = (const float*)d_in[13];
    const float* mq_Wa    = (const float*)d_in[14];
    const float* mq_ba    = (const float*)d_in[15];
    const float* mq_Wih   = (const float*)d_in[16];
    const float* mq_Whh   = (const float*)d_in[17];
    const float* mq_b     = (const float*)d_in[18];
    float* out = (float*)d_out;

    float* s = nullptr;
    cudaGetSymbolAddress((void**)&s, g_scratch);

    float* X0p = s + O_X0p;
    float* X0q = s + O_X0q;
    float* Hp0 = s + O_Hp0;
    float* Hq0 = s + O_Hq0;
    float* Hp1 = s + O_Hp1;
    float* Hq1 = s + O_Hq1;
    float* aqb = s + O_aq;
    float* apb = s + O_ap;
    float* xpb = s + O_xp;
    float* Yqb = s + O_Yq;
    unsigned* WcatB = (unsigned*)(s + O_WCB);

    cudaFuncSetAttribute(match_scan, cudaFuncAttributeMaxDynamicSharedMemorySize,
                         MATCH_SMEM_BYTES);

    // ---- Launch 1: pre0 GEMMs (passage + question) + WcatB pack tail ----
    {
        GemmCfg4 cf;
        cf.c[0] = mk(passage,  pre0_Wih, pre0_b, X0p, TPLEN * BATCH, 384, 344, 344, 0);
        cf.c[1] = mk(question, pre0_Wih, pre0_b, X0q, TQLEN * BATCH, 384, 344, 344, 0);
        cf.c[2] = cf.c[0]; cf.c[3] = cf.c[0];
        int nb = cf.c[0].nbx * cf.c[0].nby + cf.c[1].nbx * cf.c[1].nby;  // 900 + 90
        gemm_fused<<<nb + 64, 256>>>(cf, 2, nb, mq_Wh, mq_Whh, WcatB);
    }
    // ---- Launch 2: pre0 scans ----
    pre_scan_fused<<<256, 384>>>(X0p, X0q, mask_p, mask_q, pre0_Whh, Hp0, Hq0);

    // ---- Launch 3: pre1 GEMM (concatenated passage+question rows) ----
    {
        GemmCfg4 cf;
        cf.c[0] = mk(Hp0, pre1_Wih, pre1_b, X0p, (TPLEN + TQLEN) * BATCH, 384, 256, 256, 0);
        cf.c[1] = cf.c[0]; cf.c[2] = cf.c[0]; cf.c[3] = cf.c[0];
        int nb = cf.c[0].nbx * cf.c[0].nby;  // 330*3 = 990
        gemm_fused<<<nb, 256>>>(cf, 1, nb, nullptr, nullptr, nullptr);
    }
    // ---- Launch 4: pre1 scans ----
    pre_scan_fused<<<256, 384>>>(X0p, X0q, mask_p, mask_q, pre1_Whh, Hp1, Hq1);

    // ---- Launch 5: match precompute GEMMs (all four fused; biggest first) ----
    {
        GemmCfg4 cf;
        cf.c[0] = mk(Hp1, mq_Wih, mq_b,    xpb, TPLEN * BATCH, 512, 256, 512, 0);
        cf.c[1] = mk(Hp1, mq_Wp,  mq_bp,   apb, TPLEN * BATCH, 256, 256, 256, 0);
        cf.c[2] = mk(Hq1, mq_Wih, nullptr, Yqb, TQLEN * BATCH, 512, 256, 512, 256);
        cf.c[3] = mk(Hq1, mq_Wq,  nullptr, aqb, TQLEN * BATCH, 256, 256, 256, 0);
        int nb = 0;
        for (int i = 0; i < 4; i++) nb += cf.c[i].nbx * cf.c[i].nby;  // 1200+600+120+60 = 1980
        gemm_fused<<<nb, 256>>>(cf, 4, nb, nullptr, nullptr, nullptr);
    }

    // ---- Launch 6: match scan (ncu -s 5 -c 1 captures THIS) ----
    match_scan<<<2 * BATCH, 512, MATCH_SMEM_BYTES>>>(
        apb, xpb, aqb, Yqb, WcatB, mq_Wa, mq_ba, mask_p, out);

    (void)in_sizes; (void)n_in; (void)out_size;
}